// round 6
// baseline (speedup 1.0000x reference)
#include <cuda_runtime.h>
#include <math.h>

// ----- problem dims -----
#define B_    32
#define T_    100
#define NN_   32
#define F_    8
#define D_    256
#define LH    512
#define G4    2048      // 4*LH
#define ROWS  3200      // B_*T_  (row = t*32 + b)
#define NBLK  128       // persistent LSTM grid

typedef unsigned long long ull;

// ----- device scratch -----
__device__ float d_G   [ROWS * D_];
__device__ float d_F1  [G4 * D_];     // w_ih @ Wop
__device__ float d_Wbig[G4 * D_];     // w_ih @ Wop @ Wv
__device__ float d_batt[D_];          // Wop@bv + bop
__device__ float d_bihh[G4];          // w_ih@batt + b_ih + b_hh
__device__ float d_XT  [G4 * ROWS];   // X^T: [gate*512+j][t*32+b]
// hidden state, float4-grouped k-major: element (j,b) at (j>>2)*128 + b*4 + (j&3)
__device__ float d_hbuf[2][B_ * LH];
__device__ float d_LT  [LH * ROWS];   // L^T: [j][t*32+b]
__device__ float d_H1  [ROWS * D_];
__device__ int   d_flag[T_ * NBLK];   // per-(step,block) arrival flags

__device__ __forceinline__ void ffma2(ull& d, ull a, ull b) {
    asm("fma.rn.f32x2 %0, %1, %2, %0;" : "+l"(d) : "l"(a), "l"(b));
}
__device__ __forceinline__ float tanh_fast(float x) {
    float ax = fabsf(x);
    float e  = __expf(-2.0f * ax);
    float t  = __fdividef(1.0f - e, 1.0f + e);
    return copysignf(t, x);
}
__device__ __forceinline__ float sigm(float x) {
    return 1.0f / (1.0f + __expf(-x));
}

// ======================================================================
__global__ void k_zero() {
    int i = blockIdx.x * blockDim.x + threadIdx.x;
    if (i < B_ * LH) d_hbuf[0][i] = 0.0f;
    if (i < T_ * NBLK) d_flag[i] = 0;
}

// ======================================================================
// GEMV (warp-per-row): out[j] = dot(W[j,:K], x) + add1[j] (+ add2[j])
// ======================================================================
__global__ void k_gemv(const float* __restrict__ W, int K,
                       const float* __restrict__ x,
                       const float* __restrict__ add1,
                       const float* __restrict__ add2,
                       float* __restrict__ out, int M) {
    int gw   = (blockIdx.x * blockDim.x + threadIdx.x) >> 5;
    int lane = threadIdx.x & 31;
    if (gw >= M) return;
    float s = 0.0f;
    for (int k = lane; k < K; k += 32)
        s += W[(size_t)gw * K + k] * x[k];
    #pragma unroll
    for (int off = 16; off > 0; off >>= 1)
        s += __shfl_xor_sync(0xffffffff, s, off);
    if (lane == 0) {
        float r = s + add1[gw];
        if (add2) r += add2[gw];
        out[gw] = r;
    }
}

// ======================================================================
// G[row,d] = relu( (mean_n traj[b,t,n,:]) @ gcn_w + gcn_b )
// ======================================================================
__global__ void k_G(const float* __restrict__ traj,
                    const float* __restrict__ gw,
                    const float* __restrict__ gb) {
    int row = blockIdx.x;
    int t = row >> 5, b = row & 31;
    __shared__ float s[NN_ * F_];
    __shared__ float m[F_];
    int tid = threadIdx.x;
    const float* p = traj + (size_t)((b * T_ + t) * NN_) * F_;
    s[tid] = p[tid];
    __syncthreads();
    if (tid < F_) {
        float acc = 0.0f;
        #pragma unroll
        for (int n = 0; n < NN_; n++) acc += s[n * F_ + tid];
        m[tid] = acc * (1.0f / 32.0f);
    }
    __syncthreads();
    float acc = gb[tid];
    #pragma unroll
    for (int f = 0; f < F_; f++) acc += m[f] * gw[f * D_ + tid];
    d_G[(size_t)row * D_ + tid] = fmaxf(acc, 0.0f);
}

// ======================================================================
// SGEMM-NT: C[M,N] = A[M,K] @ B[N,K]^T + biasM[m]
// BM=BN=128, BK=16, 256 threads, 8x8 micro-tile. Bias indexed by ROW m.
// ======================================================================
__global__ void __launch_bounds__(256)
sgemm_nt_bm(const float* __restrict__ A, const float* __restrict__ Bm,
            const float* __restrict__ biasM, float* __restrict__ C,
            int M, int N, int K) {
    __shared__ __align__(16) float As[16][128];
    __shared__ __align__(16) float Bs[16][128];

    int tid = threadIdx.x;
    int m0 = blockIdx.y * 128, n0 = blockIdx.x * 128;
    int tm = (tid >> 4) * 8, tn = (tid & 15) * 8;

    float acc[8][8];
    #pragma unroll
    for (int i = 0; i < 8; i++)
        #pragma unroll
        for (int j = 0; j < 8; j++) acc[i][j] = 0.0f;

    for (int k0 = 0; k0 < K; k0 += 16) {
        #pragma unroll
        for (int i = 0; i < 2; i++) {
            int idx = tid + i * 256;
            int r  = idx >> 2;
            int kq = (idx & 3) * 4;
            float4 va = *(const float4*)&A [(size_t)(m0 + r) * K + k0 + kq];
            As[kq + 0][r] = va.x; As[kq + 1][r] = va.y;
            As[kq + 2][r] = va.z; As[kq + 3][r] = va.w;
            float4 vb = *(const float4*)&Bm[(size_t)(n0 + r) * K + k0 + kq];
            Bs[kq + 0][r] = vb.x; Bs[kq + 1][r] = vb.y;
            Bs[kq + 2][r] = vb.z; Bs[kq + 3][r] = vb.w;
        }
        __syncthreads();
        #pragma unroll
        for (int kk = 0; kk < 16; kk++) {
            float a[8], b[8];
            *(float4*)&a[0] = *(const float4*)&As[kk][tm];
            *(float4*)&a[4] = *(const float4*)&As[kk][tm + 4];
            *(float4*)&b[0] = *(const float4*)&Bs[kk][tn];
            *(float4*)&b[4] = *(const float4*)&Bs[kk][tn + 4];
            #pragma unroll
            for (int i = 0; i < 8; i++)
                #pragma unroll
                for (int j = 0; j < 8; j++)
                    acc[i][j] += a[i] * b[j];
        }
        __syncthreads();
    }

    #pragma unroll
    for (int i = 0; i < 8; i++) {
        float bm = biasM[m0 + tm + i];
        float* crow = C + (size_t)(m0 + tm + i) * N;
        #pragma unroll
        for (int j = 0; j < 8; j += 4) {
            float4 v;
            v.x = acc[i][j + 0] + bm; v.y = acc[i][j + 1] + bm;
            v.z = acc[i][j + 2] + bm; v.w = acc[i][j + 3] + bm;
            *(float4*)&crow[n0 + tn + j] = v;
        }
    }
}

// ======================================================================
// SGEMM BM=64 BN=128 BK=16, 256 threads, 4x8 micro-tile.
// flags: 1=relu, 2=permute rows (t*32+b -> b*T+t), 4=NN (B is W[K,N]),
//        8=no bias, 16=TN (A is AT[K][M], leading dim ldat)
// ======================================================================
__global__ void __launch_bounds__(256)
sgemm64b(const float* __restrict__ A, const float* __restrict__ Bm,
         const float* __restrict__ bias, float* __restrict__ C,
         int M, int N, int K, int flags, int ldat) {
    __shared__ __align__(16) float As[16][64];
    __shared__ __align__(16) float Bs[16][128];

    int tid = threadIdx.x;
    int m0 = blockIdx.y * 64, n0 = blockIdx.x * 128;
    int tm = (tid >> 4) * 4, tn = (tid & 15) * 8;

    float acc[4][8];
    #pragma unroll
    for (int i = 0; i < 4; i++)
        #pragma unroll
        for (int j = 0; j < 8; j++) acc[i][j] = 0.0f;

    for (int k0 = 0; k0 < K; k0 += 16) {
        if (flags & 16) {  // TN: A is AT[k][m]
            int kk = tid >> 4;
            int c  = (tid & 15) * 4;
            float4 va = *(const float4*)&A[(size_t)(k0 + kk) * ldat + m0 + c];
            *(float4*)&As[kk][c] = va;
        } else {
            int r  = tid >> 2;
            int kq = (tid & 3) * 4;
            float4 va = *(const float4*)&A[(size_t)(m0 + r) * K + k0 + kq];
            As[kq + 0][r] = va.x; As[kq + 1][r] = va.y;
            As[kq + 2][r] = va.z; As[kq + 3][r] = va.w;
        }
        if (flags & 4) {   // NN: W[k][n], leading dim N
            #pragma unroll
            for (int i = 0; i < 2; i++) {
                int idx = tid + i * 256;
                int kk = idx >> 5;
                int c  = (idx & 31) * 4;
                float4 vb = *(const float4*)&Bm[(size_t)(k0 + kk) * N + n0 + c];
                *(float4*)&Bs[kk][c] = vb;
            }
        } else {           // NT: B[n][k]
            #pragma unroll
            for (int i = 0; i < 2; i++) {
                int idx = tid + i * 256;
                int r  = idx >> 2;
                int kq = (idx & 3) * 4;
                float4 vb = *(const float4*)&Bm[(size_t)(n0 + r) * K + k0 + kq];
                Bs[kq + 0][r] = vb.x; Bs[kq + 1][r] = vb.y;
                Bs[kq + 2][r] = vb.z; Bs[kq + 3][r] = vb.w;
            }
        }
        __syncthreads();
        #pragma unroll
        for (int kk = 0; kk < 16; kk++) {
            float a[4], b[8];
            *(float4*)&a[0] = *(const float4*)&As[kk][tm];
            *(float4*)&b[0] = *(const float4*)&Bs[kk][tn];
            *(float4*)&b[4] = *(const float4*)&Bs[kk][tn + 4];
            #pragma unroll
            for (int i = 0; i < 4; i++)
                #pragma unroll
                for (int j = 0; j < 8; j++)
                    acc[i][j] += a[i] * b[j];
        }
        __syncthreads();
    }

    #pragma unroll
    for (int i = 0; i < 4; i++) {
        int m = m0 + tm + i;
        float* crow;
        if (flags & 2) { int b = m & 31, tt = m >> 5; crow = C + (size_t)(b * T_ + tt) * N; }
        else           { crow = C + (size_t)m * N; }
        #pragma unroll
        for (int j = 0; j < 8; j += 4) {
            float4 v;
            v.x = acc[i][j + 0]; v.y = acc[i][j + 1];
            v.z = acc[i][j + 2]; v.w = acc[i][j + 3];
            if (!(flags & 8)) {
                v.x += bias[n0 + tn + j + 0]; v.y += bias[n0 + tn + j + 1];
                v.z += bias[n0 + tn + j + 2]; v.w += bias[n0 + tn + j + 3];
            }
            if (flags & 1) {
                v.x = fmaxf(v.x, 0.0f); v.y = fmaxf(v.y, 0.0f);
                v.z = fmaxf(v.z, 0.0f); v.w = fmaxf(v.w, 0.0f);
            }
            *(float4*)&crow[n0 + tn + j] = v;
        }
    }
}

// ======================================================================
// Persistent LSTM: 128 blocks x 256 threads.
// Decentralized flag barrier: producer writes flag[t][blk] once
// (threadfence by tid0 only, cumulativity over bar.sync); consumers
// acquire-poll all 128 flags in parallel (one per thread).
// X[t+1] prefetched during step t's GEMM (double-buffered registers).
// ======================================================================
#define SM_WS4   0
#define SM_H4    (SM_WS4 + 16 * 128 * 16)
#define SM_PACC  (SM_H4  + 128 * 32 * 16)
#define SM_CS    (SM_PACC + 8 * 16 * 32 * 4)
#define SM_TOTAL (SM_CS + 128 * 4)

__device__ __forceinline__ int ld_acq(const int* p) {
    int v;
    asm volatile("ld.acquire.gpu.global.b32 %0, [%1];" : "=r"(v) : "l"(p));
    return v;
}

__global__ void __launch_bounds__(256, 1)
k_lstm(const float* __restrict__ whh) {
    extern __shared__ char smem[];
    float4* ws4  = (float4*)(smem + SM_WS4);   // [r][q]  r=gate*4+jj
    float4* h4   = (float4*)(smem + SM_H4);    // [q][b]
    float*  pacc = (float*) (smem + SM_PACC);  // [w][r][b]
    float*  cs   = (float*) (smem + SM_CS);    // [jj][b]

    int tid = threadIdx.x, lane = tid & 31, wrp = tid >> 5;
    int j0 = blockIdx.x * 4;

    // stage w_hh slice once
    #pragma unroll
    for (int i = 0; i < 8; i++) {
        int idx = i * 256 + tid;
        int r = idx >> 7, q = idx & 127;
        int rr = (r >> 2) * LH + j0 + (r & 3);
        ws4[r * 128 + q] = ((const float4*)whh)[(size_t)rr * 128 + q];
    }
    if (tid < 128) cs[tid] = 0.0f;
    __syncthreads();

    const int qbase = wrp * 16;
    const int pjj = tid >> 5;      // valid when tid < 128
    const int pb  = tid & 31;
    const size_t xbase = (size_t)(j0 + pjj) * ROWS + pb;
    const size_t gstr  = (size_t)LH * ROWS;

    // prefetch X for t=0
    float xg0 = 0, xg1 = 0, xg2 = 0, xg3 = 0;
    if (tid < 128) {
        xg0 = __ldcg(&d_XT[xbase + 0 * gstr]);
        xg1 = __ldcg(&d_XT[xbase + 1 * gstr]);
        xg2 = __ldcg(&d_XT[xbase + 2 * gstr]);
        xg3 = __ldcg(&d_XT[xbase + 3 * gstr]);
    }

    for (int t = 0; t < T_; t++) {
        // stage h: coalesced LDG.128 -> STS.128
        const float4* hin = (const float4*)d_hbuf[t & 1];
        #pragma unroll
        for (int i = 0; i < 16; i++) {
            int idx = i * 256 + tid;        // == q*32 + b
            h4[idx] = __ldcg(&hin[idx]);
        }
        __syncthreads();

        // prefetch next X during GEMM
        float xn0 = 0, xn1 = 0, xn2 = 0, xn3 = 0;
        if (tid < 128 && t + 1 < T_) {
            size_t o = xbase + (t + 1) * 32;
            xn0 = __ldcg(&d_XT[o + 0 * gstr]);
            xn1 = __ldcg(&d_XT[o + 1 * gstr]);
            xn2 = __ldcg(&d_XT[o + 2 * gstr]);
            xn3 = __ldcg(&d_XT[o + 3 * gstr]);
        }

        // packed GEMM: warp owns q-slice [qbase, qbase+16)
        ull alo[16], ahi[16];
        #pragma unroll
        for (int r = 0; r < 16; r++) { alo[r] = 0ULL; ahi[r] = 0ULL; }
        #pragma unroll
        for (int qq = 0; qq < 16; qq++) {
            float4 hv = h4[(qbase + qq) * 32 + lane];
            ull hlo = ((ull*)&hv)[0], hhi = ((ull*)&hv)[1];
            #pragma unroll
            for (int r = 0; r < 16; r++) {
                float4 wv = ws4[r * 128 + qbase + qq];
                ffma2(alo[r], ((ull*)&wv)[0], hlo);
                ffma2(ahi[r], ((ull*)&wv)[1], hhi);
            }
        }
        #pragma unroll
        for (int r = 0; r < 16; r++) {
            float2 a = *(float2*)&alo[r], b = *(float2*)&ahi[r];
            pacc[(wrp * 16 + r) * 32 + lane] = a.x + a.y + b.x + b.y;
        }
        __syncthreads();

        // merged reduce + pointwise (tid < 128): warp=jj, lane=b
        if (tid < 128) {
            float zi = xg0, zf = xg1, zg = xg2, zo = xg3;
            #pragma unroll
            for (int w = 0; w < 8; w++) {
                const float* pw = pacc + (w * 16) * 32 + pb;
                zi += pw[( 0 + pjj) * 32];
                zf += pw[( 4 + pjj) * 32];
                zg += pw[( 8 + pjj) * 32];
                zo += pw[(12 + pjj) * 32];
            }
            float cp = cs[pjj * 32 + pb];
            float ig = sigm(zi), fg = sigm(zf);
            float gg = tanh_fast(zg), og = sigm(zo);
            float cn = fg * cp + ig * gg;
            float hn = og * tanh_fast(cn);
            cs[pjj * 32 + pb] = cn;
            d_hbuf[(t + 1) & 1][blockIdx.x * 128 + pb * 4 + pjj] = hn;
            d_LT[(size_t)(j0 + pjj) * ROWS + t * 32 + pb] = hn;
        }
        xg0 = xn0; xg1 = xn1; xg2 = xn2; xg3 = xn3;

        // arrive: one fence + one flag store per block
        __syncthreads();
        if (tid == 0) {
            __threadfence();
            asm volatile("st.relaxed.gpu.global.b32 [%0], %1;"
                         :: "l"(&d_flag[t * NBLK + blockIdx.x]), "r"(1));
        }
        // wait: 128 threads each poll one block's flag
        if (tid < NBLK) {
            const int* f = &d_flag[t * NBLK + tid];
            while (ld_acq(f) == 0) { }
        }
        __syncthreads();
    }
}

// ======================================================================
extern "C" void kernel_launch(void* const* d_in, const int* in_sizes, int n_in,
                              void* d_out, int out_size) {
    const float* traj      = (const float*)d_in[0];
    const float* gcn_w     = (const float*)d_in[1];
    const float* gcn_b     = (const float*)d_in[2];
    const float* in_proj_w = (const float*)d_in[3];
    const float* in_proj_b = (const float*)d_in[4];
    const float* out_proj_w= (const float*)d_in[5];
    const float* out_proj_b= (const float*)d_in[6];
    // d_in[7]=va_w, d_in[8]=va_b : unused (uniform softmaxes)
    const float* w_ih      = (const float*)d_in[9];
    const float* w_hh      = (const float*)d_in[10];
    const float* b_ih      = (const float*)d_in[11];
    const float* b_hh      = (const float*)d_in[12];
    const float* lin1_w    = (const float*)d_in[13];
    const float* lin1_b    = (const float*)d_in[14];
    const float* lin2_w    = (const float*)d_in[15];
    const float* lin2_b    = (const float*)d_in[16];
    float* out = (float*)d_out;

    float *pG, *pF1, *pWbig, *pbatt, *pbihh, *pXT, *pLT, *pH1;
    cudaGetSymbolAddress((void**)&pG,    d_G);
    cudaGetSymbolAddress((void**)&pF1,   d_F1);
    cudaGetSymbolAddress((void**)&pWbig, d_Wbig);
    cudaGetSymbolAddress((void**)&pbatt, d_batt);
    cudaGetSymbolAddress((void**)&pbihh, d_bihh);
    cudaGetSymbolAddress((void**)&pXT,   d_XT);
    cudaGetSymbolAddress((void**)&pLT,   d_LT);
    cudaGetSymbolAddress((void**)&pH1,   d_H1);

    static int smem_set = 0;
    if (!smem_set) {
        cudaFuncSetAttribute(k_lstm, cudaFuncAttributeMaxDynamicSharedMemorySize,
                             SM_TOTAL);
        smem_set = 1;
    }

    const float* bv = in_proj_b + 2 * D_;

    k_zero<<<64, 256>>>();
    k_G<<<ROWS, 256>>>(traj, gcn_w, gcn_b);

    // bias_att = Wop @ bv + bop
    k_gemv<<<32, 256>>>(out_proj_w, D_, bv, out_proj_b, nullptr, pbatt, D_);
    // bias_x = w_ih @ bias_att + b_ih + b_hh
    k_gemv<<<256, 256>>>(w_ih, D_, pbatt, b_ih, b_hh, pbihh, G4);

    // F1 = w_ih @ Wop   (NN, no bias)
    sgemm64b<<<dim3(D_ / 128, G4 / 64), 256>>>(
        w_ih, out_proj_w, nullptr, pF1, G4, D_, D_, 4 | 8, 0);
    // Wbig = F1 @ Wv    (NN, no bias)
    sgemm64b<<<dim3(D_ / 128, G4 / 64), 256>>>(
        pF1, in_proj_w + (size_t)2 * D_ * D_, nullptr, pWbig, G4, D_, D_, 4 | 8, 0);

    // XT = Wbig @ G^T + bias_x[m]   (M=2048, N=3200, K=256)
    sgemm_nt_bm<<<dim3(ROWS / 128, G4 / 128), 256>>>(
        pWbig, pG, pbihh, pXT, G4, ROWS, D_);

    // persistent LSTM (writes LT)
    k_lstm<<<NBLK, 256, SM_TOTAL>>>(w_hh);

    // H1 = relu(L @ lin1_w^T + b)  via TN: A = LT[k][m], ldat=3200
    sgemm64b<<<dim3(D_ / 128, ROWS / 64), 256>>>(
        pLT, lin1_w, lin1_b, pH1, ROWS, D_, LH, 1 | 16, ROWS);

    // out = H1 @ lin2_w^T + b, permuted store
    sgemm64b<<<dim3(128 / 128, ROWS / 64), 256>>>(
        pH1, lin2_w, lin2_b, out, ROWS, 128, D_, 2, 0);
}

// round 7
// speedup vs baseline: 1.3206x; 1.3206x over previous
#include <cuda_runtime.h>
#include <math.h>

// ----- problem dims -----
#define B_    32
#define T_    100
#define NN_   32
#define F_    8
#define D_    256
#define LH    512
#define G4    2048      // 4*LH
#define ROWS  3200      // B_*T_  (row = t*32 + b)
#define NBLK  128       // persistent LSTM grid

typedef unsigned long long ull;

// ----- device scratch -----
__device__ float d_G   [ROWS * D_];
__device__ float d_F1  [G4 * D_];     // w_ih @ Wop
__device__ float d_Wbig[G4 * D_];     // w_ih @ Wop @ Wv
__device__ float d_batt[D_];          // Wop@bv + bop
__device__ float d_bihh[G4];          // w_ih@batt + b_ih + b_hh
__device__ float d_XT  [G4 * ROWS];   // X^T: [gate*512+j][t*32+b]
// hidden state, float4-grouped k-major: element (j,b) at (j>>2)*128 + b*4 + (j&3)
__device__ float d_hbuf[2][B_ * LH];
__device__ float d_LT  [LH * ROWS];   // L^T: [j][t*32+b]
__device__ float d_H1  [ROWS * D_];
__device__ int   d_bar;               // central barrier counter

__device__ __forceinline__ void ffma2(ull& d, ull a, ull b) {
    asm("fma.rn.f32x2 %0, %1, %2, %0;" : "+l"(d) : "l"(a), "l"(b));
}
__device__ __forceinline__ ull dup2(float v) {
    float2 f = make_float2(v, v);
    return *(ull*)&f;
}
__device__ __forceinline__ float tanh_fast(float x) {
    float ax = fabsf(x);
    float e  = __expf(-2.0f * ax);
    float t  = __fdividef(1.0f - e, 1.0f + e);
    return copysignf(t, x);
}
__device__ __forceinline__ float sigm(float x) {
    return 1.0f / (1.0f + __expf(-x));
}

// ======================================================================
__global__ void k_zero() {
    int i = blockIdx.x * blockDim.x + threadIdx.x;
    if (i < B_ * LH) d_hbuf[0][i] = 0.0f;
    if (i == 0) d_bar = 0;
}

// ======================================================================
// GEMV (warp-per-row): out[j] = dot(W[j,:K], x) + add1[j] (+ add2[j])
// ======================================================================
__global__ void k_gemv(const float* __restrict__ W, int K,
                       const float* __restrict__ x,
                       const float* __restrict__ add1,
                       const float* __restrict__ add2,
                       float* __restrict__ out, int M) {
    int gw   = (blockIdx.x * blockDim.x + threadIdx.x) >> 5;
    int lane = threadIdx.x & 31;
    if (gw >= M) return;
    float s = 0.0f;
    for (int k = lane; k < K; k += 32)
        s += W[(size_t)gw * K + k] * x[k];
    #pragma unroll
    for (int off = 16; off > 0; off >>= 1)
        s += __shfl_xor_sync(0xffffffff, s, off);
    if (lane == 0) {
        float r = s + add1[gw];
        if (add2) r += add2[gw];
        out[gw] = r;
    }
}

// ======================================================================
// G[row,d] = relu( (mean_n traj[b,t,n,:]) @ gcn_w + gcn_b )
// ======================================================================
__global__ void k_G(const float* __restrict__ traj,
                    const float* __restrict__ gw,
                    const float* __restrict__ gb) {
    int row = blockIdx.x;
    int t = row >> 5, b = row & 31;
    __shared__ float s[NN_ * F_];
    __shared__ float m[F_];
    int tid = threadIdx.x;
    const float* p = traj + (size_t)((b * T_ + t) * NN_) * F_;
    s[tid] = p[tid];
    __syncthreads();
    if (tid < F_) {
        float acc = 0.0f;
        #pragma unroll
        for (int n = 0; n < NN_; n++) acc += s[n * F_ + tid];
        m[tid] = acc * (1.0f / 32.0f);
    }
    __syncthreads();
    float acc = gb[tid];
    #pragma unroll
    for (int f = 0; f < F_; f++) acc += m[f] * gw[f * D_ + tid];
    d_G[(size_t)row * D_ + tid] = fmaxf(acc, 0.0f);
}

// ======================================================================
// Packed f32x2 SGEMM-NT: C[M,N] = A[M,K] @ B[N,K]^T + biasM[m]
// BM=BN=128, BK=16, 256 threads; 4 m-pairs x 8 n per thread.
// (structure validated as R3's sgemm128)
// ======================================================================
__global__ void __launch_bounds__(256, 1)
sgemm_nt_bm_p2(const float* __restrict__ A, const float* __restrict__ Bm,
               const float* __restrict__ biasM, float* __restrict__ C,
               int M, int N, int K) {
    __shared__ __align__(16) float As[16][128];
    __shared__ __align__(16) ull   BsD[16][128];   // duplicated pairs

    int tid = threadIdx.x;
    int m0 = blockIdx.y * 128, n0 = blockIdx.x * 128;
    int tm = (tid >> 4) * 8, tn = (tid & 15) * 8;

    ull acc[4][8];
    #pragma unroll
    for (int i = 0; i < 4; i++)
        #pragma unroll
        for (int j = 0; j < 8; j++) acc[i][j] = 0ULL;

    for (int k0 = 0; k0 < K; k0 += 16) {
        #pragma unroll
        for (int i = 0; i < 2; i++) {
            int idx = tid + i * 256;
            int r  = idx >> 2;
            int kq = (idx & 3) * 4;
            float4 va = *(const float4*)&A [(size_t)(m0 + r) * K + k0 + kq];
            As[kq + 0][r] = va.x; As[kq + 1][r] = va.y;
            As[kq + 2][r] = va.z; As[kq + 3][r] = va.w;
            float4 vb = *(const float4*)&Bm[(size_t)(n0 + r) * K + k0 + kq];
            BsD[kq + 0][r] = dup2(vb.x); BsD[kq + 1][r] = dup2(vb.y);
            BsD[kq + 2][r] = dup2(vb.z); BsD[kq + 3][r] = dup2(vb.w);
        }
        __syncthreads();
        #pragma unroll
        for (int kk = 0; kk < 16; kk++) {
            float4 a03 = *(const float4*)&As[kk][tm];
            float4 a47 = *(const float4*)&As[kk][tm + 4];
            ull ap[4] = { ((ull*)&a03)[0], ((ull*)&a03)[1],
                          ((ull*)&a47)[0], ((ull*)&a47)[1] };
            ull bq[8];
            *(float4*)&bq[0] = *(const float4*)&BsD[kk][tn + 0];
            *(float4*)&bq[2] = *(const float4*)&BsD[kk][tn + 2];
            *(float4*)&bq[4] = *(const float4*)&BsD[kk][tn + 4];
            *(float4*)&bq[6] = *(const float4*)&BsD[kk][tn + 6];
            #pragma unroll
            for (int i = 0; i < 4; i++)
                #pragma unroll
                for (int j = 0; j < 8; j++)
                    ffma2(acc[i][j], ap[i], bq[j]);
        }
        __syncthreads();
    }

    #pragma unroll
    for (int i = 0; i < 4; i++) {
        #pragma unroll
        for (int h = 0; h < 2; h++) {
            int m = m0 + tm + 2 * i + h;
            float bm = biasM[m];
            float* crow = C + (size_t)m * N;
            #pragma unroll
            for (int j = 0; j < 8; j += 4) {
                float4 v;
                float2 u0 = *(float2*)&acc[i][j + 0];
                float2 u1 = *(float2*)&acc[i][j + 1];
                float2 u2 = *(float2*)&acc[i][j + 2];
                float2 u3 = *(float2*)&acc[i][j + 3];
                v.x = (h ? u0.y : u0.x) + bm;
                v.y = (h ? u1.y : u1.x) + bm;
                v.z = (h ? u2.y : u2.x) + bm;
                v.w = (h ? u3.y : u3.x) + bm;
                *(float4*)&crow[n0 + tn + j] = v;
            }
        }
    }
}

// ======================================================================
// SGEMM BM=64 BN=128 BK=16, 256 threads, 4x8 micro-tile.
// flags: 1=relu, 2=permute rows (t*32+b -> b*T+t), 4=NN (B is W[K,N]),
//        8=no bias, 16=TN (A is AT[K][M], leading dim ldat)
// ======================================================================
__global__ void __launch_bounds__(256)
sgemm64b(const float* __restrict__ A, const float* __restrict__ Bm,
         const float* __restrict__ bias, float* __restrict__ C,
         int M, int N, int K, int flags, int ldat) {
    __shared__ __align__(16) float As[16][64];
    __shared__ __align__(16) float Bs[16][128];

    int tid = threadIdx.x;
    int m0 = blockIdx.y * 64, n0 = blockIdx.x * 128;
    int tm = (tid >> 4) * 4, tn = (tid & 15) * 8;

    float acc[4][8];
    #pragma unroll
    for (int i = 0; i < 4; i++)
        #pragma unroll
        for (int j = 0; j < 8; j++) acc[i][j] = 0.0f;

    for (int k0 = 0; k0 < K; k0 += 16) {
        if (flags & 16) {  // TN: A is AT[k][m]
            int kk = tid >> 4;
            int c  = (tid & 15) * 4;
            float4 va = *(const float4*)&A[(size_t)(k0 + kk) * ldat + m0 + c];
            *(float4*)&As[kk][c] = va;
        } else {
            int r  = tid >> 2;
            int kq = (tid & 3) * 4;
            float4 va = *(const float4*)&A[(size_t)(m0 + r) * K + k0 + kq];
            As[kq + 0][r] = va.x; As[kq + 1][r] = va.y;
            As[kq + 2][r] = va.z; As[kq + 3][r] = va.w;
        }
        if (flags & 4) {   // NN: W[k][n], leading dim N
            #pragma unroll
            for (int i = 0; i < 2; i++) {
                int idx = tid + i * 256;
                int kk = idx >> 5;
                int c  = (idx & 31) * 4;
                float4 vb = *(const float4*)&Bm[(size_t)(k0 + kk) * N + n0 + c];
                *(float4*)&Bs[kk][c] = vb;
            }
        } else {           // NT: B[n][k]
            #pragma unroll
            for (int i = 0; i < 2; i++) {
                int idx = tid + i * 256;
                int r  = idx >> 2;
                int kq = (idx & 3) * 4;
                float4 vb = *(const float4*)&Bm[(size_t)(n0 + r) * K + k0 + kq];
                Bs[kq + 0][r] = vb.x; Bs[kq + 1][r] = vb.y;
                Bs[kq + 2][r] = vb.z; Bs[kq + 3][r] = vb.w;
            }
        }
        __syncthreads();
        #pragma unroll
        for (int kk = 0; kk < 16; kk++) {
            float a[4], b[8];
            *(float4*)&a[0] = *(const float4*)&As[kk][tm];
            *(float4*)&b[0] = *(const float4*)&Bs[kk][tn];
            *(float4*)&b[4] = *(const float4*)&Bs[kk][tn + 4];
            #pragma unroll
            for (int i = 0; i < 4; i++)
                #pragma unroll
                for (int j = 0; j < 8; j++)
                    acc[i][j] += a[i] * b[j];
        }
        __syncthreads();
    }

    #pragma unroll
    for (int i = 0; i < 4; i++) {
        int m = m0 + tm + i;
        float* crow;
        if (flags & 2) { int b = m & 31, tt = m >> 5; crow = C + (size_t)(b * T_ + tt) * N; }
        else           { crow = C + (size_t)m * N; }
        #pragma unroll
        for (int j = 0; j < 8; j += 4) {
            float4 v;
            v.x = acc[i][j + 0]; v.y = acc[i][j + 1];
            v.z = acc[i][j + 2]; v.w = acc[i][j + 3];
            if (!(flags & 8)) {
                v.x += bias[n0 + tn + j + 0]; v.y += bias[n0 + tn + j + 1];
                v.z += bias[n0 + tn + j + 2]; v.w += bias[n0 + tn + j + 3];
            }
            if (flags & 1) {
                v.x = fmaxf(v.x, 0.0f); v.y = fmaxf(v.y, 0.0f);
                v.z = fmaxf(v.z, 0.0f); v.w = fmaxf(v.w, 0.0f);
            }
            *(float4*)&crow[n0 + tn + j] = v;
        }
    }
}

// ======================================================================
// Persistent LSTM: 128 blocks x 256 threads.
// Central-atomic barrier (R5 proven); X register double-buffering.
// ======================================================================
#define SM_WS4   0
#define SM_H4    (SM_WS4 + 16 * 128 * 16)
#define SM_PACC  (SM_H4  + 128 * 32 * 16)
#define SM_CS    (SM_PACC + 8 * 16 * 32 * 4)
#define SM_TOTAL (SM_CS + 128 * 4)

__global__ void __launch_bounds__(256, 1)
k_lstm(const float* __restrict__ whh) {
    extern __shared__ char smem[];
    float4* ws4  = (float4*)(smem + SM_WS4);   // [r][q]  r=gate*4+jj
    float4* h4   = (float4*)(smem + SM_H4);    // [q][b]
    float*  pacc = (float*) (smem + SM_PACC);  // [w][r][b]
    float*  cs   = (float*) (smem + SM_CS);    // [jj][b]

    int tid = threadIdx.x, lane = tid & 31, wrp = tid >> 5;
    int j0 = blockIdx.x * 4;

    // stage w_hh slice once
    #pragma unroll
    for (int i = 0; i < 8; i++) {
        int idx = i * 256 + tid;
        int r = idx >> 7, q = idx & 127;
        int rr = (r >> 2) * LH + j0 + (r & 3);
        ws4[r * 128 + q] = ((const float4*)whh)[(size_t)rr * 128 + q];
    }
    if (tid < 128) cs[tid] = 0.0f;
    __syncthreads();

    const int qbase = wrp * 16;
    const int pjj = tid >> 5;      // valid when tid < 128
    const int pb  = tid & 31;
    const size_t xbase = (size_t)(j0 + pjj) * ROWS + pb;
    const size_t gstr  = (size_t)LH * ROWS;

    // prefetch X for t=0
    float xg0 = 0, xg1 = 0, xg2 = 0, xg3 = 0;
    if (tid < 128) {
        xg0 = __ldcg(&d_XT[xbase + 0 * gstr]);
        xg1 = __ldcg(&d_XT[xbase + 1 * gstr]);
        xg2 = __ldcg(&d_XT[xbase + 2 * gstr]);
        xg3 = __ldcg(&d_XT[xbase + 3 * gstr]);
    }

    for (int t = 0; t < T_; t++) {
        // stage h: coalesced LDG.128 -> STS.128
        const float4* hin = (const float4*)d_hbuf[t & 1];
        #pragma unroll
        for (int i = 0; i < 16; i++) {
            int idx = i * 256 + tid;        // == q*32 + b
            h4[idx] = __ldcg(&hin[idx]);
        }
        __syncthreads();

        // prefetch next X during GEMM
        float xn0 = 0, xn1 = 0, xn2 = 0, xn3 = 0;
        if (tid < 128 && t + 1 < T_) {
            size_t o = xbase + (t + 1) * 32;
            xn0 = __ldcg(&d_XT[o + 0 * gstr]);
            xn1 = __ldcg(&d_XT[o + 1 * gstr]);
            xn2 = __ldcg(&d_XT[o + 2 * gstr]);
            xn3 = __ldcg(&d_XT[o + 3 * gstr]);
        }

        // packed GEMM: warp owns q-slice [qbase, qbase+16)
        ull alo[16], ahi[16];
        #pragma unroll
        for (int r = 0; r < 16; r++) { alo[r] = 0ULL; ahi[r] = 0ULL; }
        #pragma unroll
        for (int qq = 0; qq < 16; qq++) {
            float4 hv = h4[(qbase + qq) * 32 + lane];
            ull hlo = ((ull*)&hv)[0], hhi = ((ull*)&hv)[1];
            #pragma unroll
            for (int r = 0; r < 16; r++) {
                float4 wv = ws4[r * 128 + qbase + qq];
                ffma2(alo[r], ((ull*)&wv)[0], hlo);
                ffma2(ahi[r], ((ull*)&wv)[1], hhi);
            }
        }
        #pragma unroll
        for (int r = 0; r < 16; r++) {
            float2 a = *(float2*)&alo[r], b = *(float2*)&ahi[r];
            pacc[(wrp * 16 + r) * 32 + lane] = a.x + a.y + b.x + b.y;
        }
        __syncthreads();

        // merged reduce + pointwise (tid < 128): warp=jj, lane=b
        if (tid < 128) {
            float zi = xg0, zf = xg1, zg = xg2, zo = xg3;
            #pragma unroll
            for (int w = 0; w < 8; w++) {
                const float* pw = pacc + (w * 16) * 32 + pb;
                zi += pw[( 0 + pjj) * 32];
                zf += pw[( 4 + pjj) * 32];
                zg += pw[( 8 + pjj) * 32];
                zo += pw[(12 + pjj) * 32];
            }
            float cp = cs[pjj * 32 + pb];
            float ig = sigm(zi), fg = sigm(zf);
            float gg = tanh_fast(zg), og = sigm(zo);
            float cn = fg * cp + ig * gg;
            float hn = og * tanh_fast(cn);
            cs[pjj * 32 + pb] = cn;
            d_hbuf[(t + 1) & 1][blockIdx.x * 128 + pb * 4 + pjj] = hn;
            d_LT[(size_t)(j0 + pjj) * ROWS + t * 32 + pb] = hn;
            __threadfence();
        }
        xg0 = xn0; xg1 = xn1; xg2 = xn2; xg3 = xn3;

        // central-atomic device-wide barrier (R5 proven)
        __syncthreads();
        if (tid == 0) {
            atomicAdd(&d_bar, 1);
            volatile int* vb = &d_bar;
            while (*vb < NBLK * (t + 1)) { }
        }
        __syncthreads();
    }
}

// ======================================================================
extern "C" void kernel_launch(void* const* d_in, const int* in_sizes, int n_in,
                              void* d_out, int out_size) {
    const float* traj      = (const float*)d_in[0];
    const float* gcn_w     = (const float*)d_in[1];
    const float* gcn_b     = (const float*)d_in[2];
    const float* in_proj_w = (const float*)d_in[3];
    const float* in_proj_b = (const float*)d_in[4];
    const float* out_proj_w= (const float*)d_in[5];
    const float* out_proj_b= (const float*)d_in[6];
    // d_in[7]=va_w, d_in[8]=va_b : unused (uniform softmaxes)
    const float* w_ih      = (const float*)d_in[9];
    const float* w_hh      = (const float*)d_in[10];
    const float* b_ih      = (const float*)d_in[11];
    const float* b_hh      = (const float*)d_in[12];
    const float* lin1_w    = (const float*)d_in[13];
    const float* lin1_b    = (const float*)d_in[14];
    const float* lin2_w    = (const float*)d_in[15];
    const float* lin2_b    = (const float*)d_in[16];
    float* out = (float*)d_out;

    float *pG, *pF1, *pWbig, *pbatt, *pbihh, *pXT, *pLT, *pH1;
    cudaGetSymbolAddress((void**)&pG,    d_G);
    cudaGetSymbolAddress((void**)&pF1,   d_F1);
    cudaGetSymbolAddress((void**)&pWbig, d_Wbig);
    cudaGetSymbolAddress((void**)&pbatt, d_batt);
    cudaGetSymbolAddress((void**)&pbihh, d_bihh);
    cudaGetSymbolAddress((void**)&pXT,   d_XT);
    cudaGetSymbolAddress((void**)&pLT,   d_LT);
    cudaGetSymbolAddress((void**)&pH1,   d_H1);

    static int smem_set = 0;
    if (!smem_set) {
        cudaFuncSetAttribute(k_lstm, cudaFuncAttributeMaxDynamicSharedMemorySize,
                             SM_TOTAL);
        smem_set = 1;
    }

    const float* bv = in_proj_b + 2 * D_;

    k_zero<<<64, 256>>>();
    k_G<<<ROWS, 256>>>(traj, gcn_w, gcn_b);

    // bias_att = Wop @ bv + bop
    k_gemv<<<32, 256>>>(out_proj_w, D_, bv, out_proj_b, nullptr, pbatt, D_);
    // bias_x = w_ih @ bias_att + b_ih + b_hh
    k_gemv<<<256, 256>>>(w_ih, D_, pbatt, b_ih, b_hh, pbihh, G4);

    // F1 = w_ih @ Wop   (NN, no bias)
    sgemm64b<<<dim3(D_ / 128, G4 / 64), 256>>>(
        w_ih, out_proj_w, nullptr, pF1, G4, D_, D_, 4 | 8, 0);
    // Wbig = F1 @ Wv    (NN, no bias)
    sgemm64b<<<dim3(D_ / 128, G4 / 64), 256>>>(
        pF1, in_proj_w + (size_t)2 * D_ * D_, nullptr, pWbig, G4, D_, D_, 4 | 8, 0);

    // XT = Wbig @ G^T + bias_x[m]   (packed f32x2, M=2048, N=3200, K=256)
    sgemm_nt_bm_p2<<<dim3(ROWS / 128, G4 / 128), 256>>>(
        pWbig, pG, pbihh, pXT, G4, ROWS, D_);

    // persistent LSTM (writes LT)
    k_lstm<<<NBLK, 256, SM_TOTAL>>>(w_hh);

    // H1 = relu(L @ lin1_w^T + b)  via TN: A = LT[k][m], ldat=3200
    sgemm64b<<<dim3(D_ / 128, ROWS / 64), 256>>>(
        pLT, lin1_w, lin1_b, pH1, ROWS, D_, LH, 1 | 16, ROWS);

    // out = H1 @ lin2_w^T + b, permuted store
    sgemm64b<<<dim3(128 / 128, ROWS / 64), 256>>>(
        pH1, lin2_w, lin2_b, out, ROWS, 128, D_, 2, 0);
}

// round 8
// speedup vs baseline: 1.6065x; 1.2165x over previous
#include <cuda_runtime.h>
#include <math.h>

// ----- problem dims -----
#define B_    32
#define T_    100
#define NN_   32
#define F_    8
#define D_    256
#define LH    512
#define G4    2048      // 4*LH
#define ROWS  3200      // B_*T_  (row = t*32 + b)
#define NBLK  128       // persistent LSTM grid

typedef unsigned long long ull;

// ----- device scratch -----
__device__ float d_G   [ROWS * D_];
__device__ float d_F1  [G4 * D_];     // w_ih @ Wop
__device__ float d_Wbig[G4 * D_];     // w_ih @ Wop @ Wv
__device__ float d_batt[D_];          // Wop@bv + bop
__device__ float d_bihh[G4];          // w_ih@batt + b_ih + b_hh
__device__ float d_XT  [G4 * ROWS];   // X^T: [gate*512+j][t*32+b]
// hidden state, float4-grouped k-major: element (j,b) at (j>>2)*128 + b*4 + (j&3)
__device__ float d_hbuf[2][B_ * LH];
__device__ float d_LT  [LH * ROWS];   // L^T: [j][t*32+b]
__device__ float d_H1  [ROWS * D_];
__device__ int   d_bar;               // central barrier counter

__device__ __forceinline__ void ffma2(ull& d, ull a, ull b) {
    asm("fma.rn.f32x2 %0, %1, %2, %0;" : "+l"(d) : "l"(a), "l"(b));
}
__device__ __forceinline__ float tanh_fast(float x) {
    float ax = fabsf(x);
    float e  = __expf(-2.0f * ax);
    float t  = __fdividef(1.0f - e, 1.0f + e);
    return copysignf(t, x);
}
__device__ __forceinline__ float sigm(float x) {
    return 1.0f / (1.0f + __expf(-x));
}
__device__ __forceinline__ void red_release_add(int* p, int v) {
    asm volatile("red.release.gpu.global.add.s32 [%0], %1;" :: "l"(p), "r"(v) : "memory");
}
__device__ __forceinline__ int ld_acq(const int* p) {
    int v;
    asm volatile("ld.acquire.gpu.global.b32 %0, [%1];" : "=r"(v) : "l"(p) : "memory");
    return v;
}

// ======================================================================
__global__ void k_zero() {
    int i = blockIdx.x * blockDim.x + threadIdx.x;
    if (i < B_ * LH) d_hbuf[0][i] = 0.0f;
    if (i == 0) d_bar = 0;
}

// ======================================================================
// GEMV (warp-per-row): out[j] = dot(W[j,:K], x) + add1[j] (+ add2[j])
// ======================================================================
__global__ void k_gemv(const float* __restrict__ W, int K,
                       const float* __restrict__ x,
                       const float* __restrict__ add1,
                       const float* __restrict__ add2,
                       float* __restrict__ out, int M) {
    int gw   = (blockIdx.x * blockDim.x + threadIdx.x) >> 5;
    int lane = threadIdx.x & 31;
    if (gw >= M) return;
    float s = 0.0f;
    for (int k = lane; k < K; k += 32)
        s += W[(size_t)gw * K + k] * x[k];
    #pragma unroll
    for (int off = 16; off > 0; off >>= 1)
        s += __shfl_xor_sync(0xffffffff, s, off);
    if (lane == 0) {
        float r = s + add1[gw];
        if (add2) r += add2[gw];
        out[gw] = r;
    }
}

// ======================================================================
// G[row,d] = relu( (mean_n traj[b,t,n,:]) @ gcn_w + gcn_b )
// ======================================================================
__global__ void k_G(const float* __restrict__ traj,
                    const float* __restrict__ gw,
                    const float* __restrict__ gb) {
    int row = blockIdx.x;
    int t = row >> 5, b = row & 31;
    __shared__ float s[NN_ * F_];
    __shared__ float m[F_];
    int tid = threadIdx.x;
    const float* p = traj + (size_t)((b * T_ + t) * NN_) * F_;
    s[tid] = p[tid];
    __syncthreads();
    if (tid < F_) {
        float acc = 0.0f;
        #pragma unroll
        for (int n = 0; n < NN_; n++) acc += s[n * F_ + tid];
        m[tid] = acc * (1.0f / 32.0f);
    }
    __syncthreads();
    float acc = gb[tid];
    #pragma unroll
    for (int f = 0; f < F_; f++) acc += m[f] * gw[f * D_ + tid];
    d_G[(size_t)row * D_ + tid] = fmaxf(acc, 0.0f);
}

// ======================================================================
// SGEMM-NT (proven, occ 2): C[M,N] = A[M,K] @ B[N,K]^T + biasM[m]
// BM=BN=128, BK=16, 256 threads, 8x8 micro-tile. Bias indexed by ROW m.
// ======================================================================
__global__ void __launch_bounds__(256)
sgemm_nt_bm(const float* __restrict__ A, const float* __restrict__ Bm,
            const float* __restrict__ biasM, float* __restrict__ C,
            int M, int N, int K) {
    __shared__ __align__(16) float As[16][128];
    __shared__ __align__(16) float Bs[16][128];

    int tid = threadIdx.x;
    int m0 = blockIdx.y * 128, n0 = blockIdx.x * 128;
    int tm = (tid >> 4) * 8, tn = (tid & 15) * 8;

    float acc[8][8];
    #pragma unroll
    for (int i = 0; i < 8; i++)
        #pragma unroll
        for (int j = 0; j < 8; j++) acc[i][j] = 0.0f;

    for (int k0 = 0; k0 < K; k0 += 16) {
        #pragma unroll
        for (int i = 0; i < 2; i++) {
            int idx = tid + i * 256;
            int r  = idx >> 2;
            int kq = (idx & 3) * 4;
            float4 va = *(const float4*)&A [(size_t)(m0 + r) * K + k0 + kq];
            As[kq + 0][r] = va.x; As[kq + 1][r] = va.y;
            As[kq + 2][r] = va.z; As[kq + 3][r] = va.w;
            float4 vb = *(const float4*)&Bm[(size_t)(n0 + r) * K + k0 + kq];
            Bs[kq + 0][r] = vb.x; Bs[kq + 1][r] = vb.y;
            Bs[kq + 2][r] = vb.z; Bs[kq + 3][r] = vb.w;
        }
        __syncthreads();
        #pragma unroll
        for (int kk = 0; kk < 16; kk++) {
            float a[8], b[8];
            *(float4*)&a[0] = *(const float4*)&As[kk][tm];
            *(float4*)&a[4] = *(const float4*)&As[kk][tm + 4];
            *(float4*)&b[0] = *(const float4*)&Bs[kk][tn];
            *(float4*)&b[4] = *(const float4*)&Bs[kk][tn + 4];
            #pragma unroll
            for (int i = 0; i < 8; i++)
                #pragma unroll
                for (int j = 0; j < 8; j++)
                    acc[i][j] += a[i] * b[j];
        }
        __syncthreads();
    }

    #pragma unroll
    for (int i = 0; i < 8; i++) {
        float bm = biasM[m0 + tm + i];
        float* crow = C + (size_t)(m0 + tm + i) * N;
        #pragma unroll
        for (int j = 0; j < 8; j += 4) {
            float4 v;
            v.x = acc[i][j + 0] + bm; v.y = acc[i][j + 1] + bm;
            v.z = acc[i][j + 2] + bm; v.w = acc[i][j + 3] + bm;
            *(float4*)&crow[n0 + tn + j] = v;
        }
    }
}

// ======================================================================
// SGEMM BM=64 BN=128 BK=16, 256 threads, 4x8 micro-tile.
// flags: 1=relu, 2=permute rows (t*32+b -> b*T+t), 4=NN (B is W[K,N]),
//        8=no bias, 16=TN (A is AT[K][M], leading dim ldat)
// ======================================================================
__global__ void __launch_bounds__(256)
sgemm64b(const float* __restrict__ A, const float* __restrict__ Bm,
         const float* __restrict__ bias, float* __restrict__ C,
         int M, int N, int K, int flags, int ldat) {
    __shared__ __align__(16) float As[16][64];
    __shared__ __align__(16) float Bs[16][128];

    int tid = threadIdx.x;
    int m0 = blockIdx.y * 64, n0 = blockIdx.x * 128;
    int tm = (tid >> 4) * 4, tn = (tid & 15) * 8;

    float acc[4][8];
    #pragma unroll
    for (int i = 0; i < 4; i++)
        #pragma unroll
        for (int j = 0; j < 8; j++) acc[i][j] = 0.0f;

    for (int k0 = 0; k0 < K; k0 += 16) {
        if (flags & 16) {  // TN: A is AT[k][m]
            int kk = tid >> 4;
            int c  = (tid & 15) * 4;
            float4 va = *(const float4*)&A[(size_t)(k0 + kk) * ldat + m0 + c];
            *(float4*)&As[kk][c] = va;
        } else {
            int r  = tid >> 2;
            int kq = (tid & 3) * 4;
            float4 va = *(const float4*)&A[(size_t)(m0 + r) * K + k0 + kq];
            As[kq + 0][r] = va.x; As[kq + 1][r] = va.y;
            As[kq + 2][r] = va.z; As[kq + 3][r] = va.w;
        }
        if (flags & 4) {   // NN: W[k][n], leading dim N
            #pragma unroll
            for (int i = 0; i < 2; i++) {
                int idx = tid + i * 256;
                int kk = idx >> 5;
                int c  = (idx & 31) * 4;
                float4 vb = *(const float4*)&Bm[(size_t)(k0 + kk) * N + n0 + c];
                *(float4*)&Bs[kk][c] = vb;
            }
        } else {           // NT: B[n][k]
            #pragma unroll
            for (int i = 0; i < 2; i++) {
                int idx = tid + i * 256;
                int r  = idx >> 2;
                int kq = (idx & 3) * 4;
                float4 vb = *(const float4*)&Bm[(size_t)(n0 + r) * K + k0 + kq];
                Bs[kq + 0][r] = vb.x; Bs[kq + 1][r] = vb.y;
                Bs[kq + 2][r] = vb.z; Bs[kq + 3][r] = vb.w;
            }
        }
        __syncthreads();
        #pragma unroll
        for (int kk = 0; kk < 16; kk++) {
            float a[4], b[8];
            *(float4*)&a[0] = *(const float4*)&As[kk][tm];
            *(float4*)&b[0] = *(const float4*)&Bs[kk][tn];
            *(float4*)&b[4] = *(const float4*)&Bs[kk][tn + 4];
            #pragma unroll
            for (int i = 0; i < 4; i++)
                #pragma unroll
                for (int j = 0; j < 8; j++)
                    acc[i][j] += a[i] * b[j];
        }
        __syncthreads();
    }

    #pragma unroll
    for (int i = 0; i < 4; i++) {
        int m = m0 + tm + i;
        float* crow;
        if (flags & 2) { int b = m & 31, tt = m >> 5; crow = C + (size_t)(b * T_ + tt) * N; }
        else           { crow = C + (size_t)m * N; }
        #pragma unroll
        for (int j = 0; j < 8; j += 4) {
            float4 v;
            v.x = acc[i][j + 0]; v.y = acc[i][j + 1];
            v.z = acc[i][j + 2]; v.w = acc[i][j + 3];
            if (!(flags & 8)) {
                v.x += bias[n0 + tn + j + 0]; v.y += bias[n0 + tn + j + 1];
                v.z += bias[n0 + tn + j + 2]; v.w += bias[n0 + tn + j + 3];
            }
            if (flags & 1) {
                v.x = fmaxf(v.x, 0.0f); v.y = fmaxf(v.y, 0.0f);
                v.z = fmaxf(v.z, 0.0f); v.w = fmaxf(v.w, 0.0f);
            }
            *(float4*)&crow[n0 + tn + j] = v;
        }
    }
}

// ======================================================================
// Persistent LSTM: 128 blocks x 256 threads.
// Barrier: bar.sync -> tid0 red.release.gpu.add -> tid0 ld.acquire spin.
// ======================================================================
#define SM_WS4   0
#define SM_H4    (SM_WS4 + 16 * 128 * 16)
#define SM_PACC  (SM_H4  + 128 * 32 * 16)
#define SM_CS    (SM_PACC + 8 * 16 * 32 * 4)
#define SM_TOTAL (SM_CS + 128 * 4)

__global__ void __launch_bounds__(256, 1)
k_lstm(const float* __restrict__ whh) {
    extern __shared__ char smem[];
    float4* ws4  = (float4*)(smem + SM_WS4);   // [r][q]  r=gate*4+jj
    float4* h4   = (float4*)(smem + SM_H4);    // [q][b]
    float*  pacc = (float*) (smem + SM_PACC);  // [w][r][b]
    float*  cs   = (float*) (smem + SM_CS);    // [jj][b]

    int tid = threadIdx.x, lane = tid & 31, wrp = tid >> 5;
    int j0 = blockIdx.x * 4;

    // stage w_hh slice once
    #pragma unroll
    for (int i = 0; i < 8; i++) {
        int idx = i * 256 + tid;
        int r = idx >> 7, q = idx & 127;
        int rr = (r >> 2) * LH + j0 + (r & 3);
        ws4[r * 128 + q] = ((const float4*)whh)[(size_t)rr * 128 + q];
    }
    if (tid < 128) cs[tid] = 0.0f;
    __syncthreads();

    const int qbase = wrp * 16;
    const int pjj = tid >> 5;      // valid when tid < 128
    const int pb  = tid & 31;
    const size_t xbase = (size_t)(j0 + pjj) * ROWS + pb;
    const size_t gstr  = (size_t)LH * ROWS;

    // prefetch X for t=0
    float xg0 = 0, xg1 = 0, xg2 = 0, xg3 = 0;
    if (tid < 128) {
        xg0 = __ldcg(&d_XT[xbase + 0 * gstr]);
        xg1 = __ldcg(&d_XT[xbase + 1 * gstr]);
        xg2 = __ldcg(&d_XT[xbase + 2 * gstr]);
        xg3 = __ldcg(&d_XT[xbase + 3 * gstr]);
    }

    for (int t = 0; t < T_; t++) {
        // stage h: coalesced LDG.128 -> STS.128
        const float4* hin = (const float4*)d_hbuf[t & 1];
        #pragma unroll
        for (int i = 0; i < 16; i++) {
            int idx = i * 256 + tid;        // == q*32 + b
            h4[idx] = __ldcg(&hin[idx]);
        }
        __syncthreads();

        // prefetch next X during GEMM
        float xn0 = 0, xn1 = 0, xn2 = 0, xn3 = 0;
        if (tid < 128 && t + 1 < T_) {
            size_t o = xbase + (t + 1) * 32;
            xn0 = __ldcg(&d_XT[o + 0 * gstr]);
            xn1 = __ldcg(&d_XT[o + 1 * gstr]);
            xn2 = __ldcg(&d_XT[o + 2 * gstr]);
            xn3 = __ldcg(&d_XT[o + 3 * gstr]);
        }

        // packed GEMM: warp owns q-slice [qbase, qbase+16)
        ull alo[16], ahi[16];
        #pragma unroll
        for (int r = 0; r < 16; r++) { alo[r] = 0ULL; ahi[r] = 0ULL; }
        #pragma unroll
        for (int qq = 0; qq < 16; qq++) {
            float4 hv = h4[(qbase + qq) * 32 + lane];
            ull hlo = ((ull*)&hv)[0], hhi = ((ull*)&hv)[1];
            #pragma unroll
            for (int r = 0; r < 16; r++) {
                float4 wv = ws4[r * 128 + qbase + qq];
                ffma2(alo[r], ((ull*)&wv)[0], hlo);
                ffma2(ahi[r], ((ull*)&wv)[1], hhi);
            }
        }
        #pragma unroll
        for (int r = 0; r < 16; r++) {
            float2 a = *(float2*)&alo[r], b = *(float2*)&ahi[r];
            pacc[(wrp * 16 + r) * 32 + lane] = a.x + a.y + b.x + b.y;
        }
        __syncthreads();

        // merged reduce + pointwise (tid < 128): warp=jj, lane=b
        if (tid < 128) {
            float zi = xg0, zf = xg1, zg = xg2, zo = xg3;
            #pragma unroll
            for (int w = 0; w < 8; w++) {
                const float* pw = pacc + (w * 16) * 32 + pb;
                zi += pw[( 0 + pjj) * 32];
                zf += pw[( 4 + pjj) * 32];
                zg += pw[( 8 + pjj) * 32];
                zo += pw[(12 + pjj) * 32];
            }
            float cp = cs[pjj * 32 + pb];
            float ig = sigm(zi), fg = sigm(zf);
            float gg = tanh_fast(zg), og = sigm(zo);
            float cn = fg * cp + ig * gg;
            float hn = og * tanh_fast(cn);
            cs[pjj * 32 + pb] = cn;
            d_hbuf[(t + 1) & 1][blockIdx.x * 128 + pb * 4 + pjj] = hn;
            d_LT[(size_t)(j0 + pjj) * ROWS + t * 32 + pb] = hn;
        }
        xg0 = xn0; xg1 = xn1; xg2 = xn2; xg3 = xn3;

        // device-wide barrier: release-add by tid0 (cumulative over bar.sync),
        // acquire-spin by tid0, then block-wide bar.sync.
        __syncthreads();
        if (tid == 0) {
            red_release_add(&d_bar, 1);
            while (ld_acq(&d_bar) < NBLK * (t + 1)) { }
        }
        __syncthreads();
    }
}

// ======================================================================
extern "C" void kernel_launch(void* const* d_in, const int* in_sizes, int n_in,
                              void* d_out, int out_size) {
    const float* traj      = (const float*)d_in[0];
    const float* gcn_w     = (const float*)d_in[1];
    const float* gcn_b     = (const float*)d_in[2];
    const float* in_proj_w = (const float*)d_in[3];
    const float* in_proj_b = (const float*)d_in[4];
    const float* out_proj_w= (const float*)d_in[5];
    const float* out_proj_b= (const float*)d_in[6];
    // d_in[7]=va_w, d_in[8]=va_b : unused (uniform softmaxes)
    const float* w_ih      = (const float*)d_in[9];
    const float* w_hh      = (const float*)d_in[10];
    const float* b_ih      = (const float*)d_in[11];
    const float* b_hh      = (const float*)d_in[12];
    const float* lin1_w    = (const float*)d_in[13];
    const float* lin1_b    = (const float*)d_in[14];
    const float* lin2_w    = (const float*)d_in[15];
    const float* lin2_b    = (const float*)d_in[16];
    float* out = (float*)d_out;

    float *pG, *pF1, *pWbig, *pbatt, *pbihh, *pXT, *pLT, *pH1;
    cudaGetSymbolAddress((void**)&pG,    d_G);
    cudaGetSymbolAddress((void**)&pF1,   d_F1);
    cudaGetSymbolAddress((void**)&pWbig, d_Wbig);
    cudaGetSymbolAddress((void**)&pbatt, d_batt);
    cudaGetSymbolAddress((void**)&pbihh, d_bihh);
    cudaGetSymbolAddress((void**)&pXT,   d_XT);
    cudaGetSymbolAddress((void**)&pLT,   d_LT);
    cudaGetSymbolAddress((void**)&pH1,   d_H1);

    static int smem_set = 0;
    if (!smem_set) {
        cudaFuncSetAttribute(k_lstm, cudaFuncAttributeMaxDynamicSharedMemorySize,
                             SM_TOTAL);
        smem_set = 1;
    }

    const float* bv = in_proj_b + 2 * D_;

    k_zero<<<64, 256>>>();
    k_G<<<ROWS, 256>>>(traj, gcn_w, gcn_b);

    // bias_att = Wop @ bv + bop
    k_gemv<<<32, 256>>>(out_proj_w, D_, bv, out_proj_b, nullptr, pbatt, D_);
    // bias_x = w_ih @ bias_att + b_ih + b_hh
    k_gemv<<<256, 256>>>(w_ih, D_, pbatt, b_ih, b_hh, pbihh, G4);

    // F1 = w_ih @ Wop   (NN, no bias)
    sgemm64b<<<dim3(D_ / 128, G4 / 64), 256>>>(
        w_ih, out_proj_w, nullptr, pF1, G4, D_, D_, 4 | 8, 0);
    // Wbig = F1 @ Wv    (NN, no bias)
    sgemm64b<<<dim3(D_ / 128, G4 / 64), 256>>>(
        pF1, in_proj_w + (size_t)2 * D_ * D_, nullptr, pWbig, G4, D_, D_, 4 | 8, 0);

    // XT = Wbig @ G^T + bias_x[m]   (scalar proven kernel, occ 2)
    sgemm_nt_bm<<<dim3(ROWS / 128, G4 / 128), 256>>>(
        pWbig, pG, pbihh, pXT, G4, ROWS, D_);

    // persistent LSTM (writes LT)
    k_lstm<<<NBLK, 256, SM_TOTAL>>>(w_hh);

    // H1 = relu(L @ lin1_w^T + b)  via TN: A = LT[k][m], ldat=3200
    sgemm64b<<<dim3(D_ / 128, ROWS / 64), 256>>>(
        pLT, lin1_w, lin1_b, pH1, ROWS, D_, LH, 1 | 16, ROWS);

    // out = H1 @ lin2_w^T + b, permuted store
    sgemm64b<<<dim3(128 / 128, ROWS / 64), 256>>>(
        pH1, lin2_w, lin2_b, out, ROWS, 128, D_, 2, 0);
}

// round 9
// speedup vs baseline: 1.6128x; 1.0039x over previous
#include <cuda_runtime.h>
#include <math.h>

// ----- problem dims -----
#define B_    32
#define T_    100
#define NN_   32
#define F_    8
#define D_    256
#define LH    512
#define G4    2048      // 4*LH
#define ROWS  3200      // B_*T_  (row = t*32 + b)
#define NBLK  128       // persistent LSTM grid

typedef unsigned long long ull;

// ----- device scratch -----
__device__ float d_G   [ROWS * D_];
__device__ float d_F1  [G4 * D_];     // w_ih @ Wop
__device__ float d_Wbig[G4 * D_];     // w_ih @ Wop @ Wv
__device__ float d_bihh[G4];          // w_ih@(Wop@bv+bop) + b_ih + b_hh
__device__ float d_XT  [G4 * ROWS];   // X^T: [gate*512+j][t*32+b]
// hidden state, float4-grouped k-major: element (j,b) at (j>>2)*128 + b*4 + (j&3)
__device__ float d_hbuf[2][B_ * LH];
__device__ float d_LT  [LH * ROWS];   // L^T: [j][t*32+b]
__device__ float d_H1  [ROWS * D_];
__device__ int   d_bar;               // central barrier counter

__device__ __forceinline__ void ffma2(ull& d, ull a, ull b) {
    asm("fma.rn.f32x2 %0, %1, %2, %0;" : "+l"(d) : "l"(a), "l"(b));
}
__device__ __forceinline__ float tanh_fast(float x) {
    float ax = fabsf(x);
    float e  = __expf(-2.0f * ax);
    float t  = __fdividef(1.0f - e, 1.0f + e);
    return copysignf(t, x);
}
__device__ __forceinline__ float sigm(float x) {
    return 1.0f / (1.0f + __expf(-x));
}
__device__ __forceinline__ void red_release_add(int* p, int v) {
    asm volatile("red.release.gpu.global.add.s32 [%0], %1;" :: "l"(p), "r"(v) : "memory");
}
__device__ __forceinline__ int ld_acq(const int* p) {
    int v;
    asm volatile("ld.acquire.gpu.global.b32 %0, [%1];" : "=r"(v) : "l"(p) : "memory");
    return v;
}

// ======================================================================
// k_init: G[row,:] = relu(mean_n(traj) @ gcn_w + gcn_b); blocks<64 also
// zero h[0]; block 0 resets barrier. (fused so k_lstm is launch #5)
// ======================================================================
__global__ void k_init(const float* __restrict__ traj,
                       const float* __restrict__ gw,
                       const float* __restrict__ gb) {
    int row = blockIdx.x;
    int t = row >> 5, b = row & 31;
    __shared__ float s[NN_ * F_];
    __shared__ float m[F_];
    int tid = threadIdx.x;

    if (row < 64) d_hbuf[0][row * 256 + tid] = 0.0f;
    if (row == 0 && tid == 0) d_bar = 0;

    const float* p = traj + (size_t)((b * T_ + t) * NN_) * F_;
    s[tid] = p[tid];
    __syncthreads();
    if (tid < F_) {
        float acc = 0.0f;
        #pragma unroll
        for (int n = 0; n < NN_; n++) acc += s[n * F_ + tid];
        m[tid] = acc * (1.0f / 32.0f);
    }
    __syncthreads();
    float acc = gb[tid];
    #pragma unroll
    for (int f = 0; f < F_; f++) acc += m[f] * gw[f * D_ + tid];
    d_G[(size_t)row * D_ + tid] = fmaxf(acc, 0.0f);
}

// ======================================================================
// k_bias (one block, 1024 threads): batt = Wop@bv + bop (smem), then
// d_bihh = w_ih@batt + b_ih + b_hh
// ======================================================================
__global__ void __launch_bounds__(1024)
k_bias(const float* __restrict__ opw, const float* __restrict__ opb,
       const float* __restrict__ bv,  const float* __restrict__ wih,
       const float* __restrict__ bih, const float* __restrict__ bhh) {
    __shared__ float batt[D_];
    int tid = threadIdx.x, lane = tid & 31, wid = tid >> 5;   // 32 warps

    for (int r = wid; r < D_; r += 32) {
        float s = 0.0f;
        for (int k = lane; k < D_; k += 32) s += opw[(size_t)r * D_ + k] * bv[k];
        #pragma unroll
        for (int off = 16; off > 0; off >>= 1) s += __shfl_xor_sync(0xffffffff, s, off);
        if (lane == 0) batt[r] = s + opb[r];
    }
    __syncthreads();
    for (int r = wid; r < G4; r += 32) {
        float s = 0.0f;
        for (int k = lane; k < D_; k += 32) s += wih[(size_t)r * D_ + k] * batt[k];
        #pragma unroll
        for (int off = 16; off > 0; off >>= 1) s += __shfl_xor_sync(0xffffffff, s, off);
        if (lane == 0) d_bihh[r] = s + bih[r] + bhh[r];
    }
}

// ======================================================================
// SGEMM-NT (proven, occ 2): C[M,N] = A[M,K] @ B[N,K]^T + biasM[m]
// BM=BN=128, BK=16, 256 threads, 8x8 micro-tile.
// ======================================================================
__global__ void __launch_bounds__(256)
sgemm_nt_bm(const float* __restrict__ A, const float* __restrict__ Bm,
            const float* __restrict__ biasM, float* __restrict__ C,
            int M, int N, int K) {
    __shared__ __align__(16) float As[16][128];
    __shared__ __align__(16) float Bs[16][128];

    int tid = threadIdx.x;
    int m0 = blockIdx.y * 128, n0 = blockIdx.x * 128;
    int tm = (tid >> 4) * 8, tn = (tid & 15) * 8;

    float acc[8][8];
    #pragma unroll
    for (int i = 0; i < 8; i++)
        #pragma unroll
        for (int j = 0; j < 8; j++) acc[i][j] = 0.0f;

    for (int k0 = 0; k0 < K; k0 += 16) {
        #pragma unroll
        for (int i = 0; i < 2; i++) {
            int idx = tid + i * 256;
            int r  = idx >> 2;
            int kq = (idx & 3) * 4;
            float4 va = *(const float4*)&A [(size_t)(m0 + r) * K + k0 + kq];
            As[kq + 0][r] = va.x; As[kq + 1][r] = va.y;
            As[kq + 2][r] = va.z; As[kq + 3][r] = va.w;
            float4 vb = *(const float4*)&Bm[(size_t)(n0 + r) * K + k0 + kq];
            Bs[kq + 0][r] = vb.x; Bs[kq + 1][r] = vb.y;
            Bs[kq + 2][r] = vb.z; Bs[kq + 3][r] = vb.w;
        }
        __syncthreads();
        #pragma unroll
        for (int kk = 0; kk < 16; kk++) {
            float a[8], b[8];
            *(float4*)&a[0] = *(const float4*)&As[kk][tm];
            *(float4*)&a[4] = *(const float4*)&As[kk][tm + 4];
            *(float4*)&b[0] = *(const float4*)&Bs[kk][tn];
            *(float4*)&b[4] = *(const float4*)&Bs[kk][tn + 4];
            #pragma unroll
            for (int i = 0; i < 8; i++)
                #pragma unroll
                for (int j = 0; j < 8; j++)
                    acc[i][j] += a[i] * b[j];
        }
        __syncthreads();
    }

    #pragma unroll
    for (int i = 0; i < 8; i++) {
        float bm = biasM[m0 + tm + i];
        float* crow = C + (size_t)(m0 + tm + i) * N;
        #pragma unroll
        for (int j = 0; j < 8; j += 4) {
            float4 v;
            v.x = acc[i][j + 0] + bm; v.y = acc[i][j + 1] + bm;
            v.z = acc[i][j + 2] + bm; v.w = acc[i][j + 3] + bm;
            *(float4*)&crow[n0 + tn + j] = v;
        }
    }
}

// ======================================================================
// SGEMM BM=64 BN=128 BK=16, 256 threads, 4x8 micro-tile.
// flags: 1=relu, 2=permute rows (t*32+b -> b*T+t), 4=NN (B is W[K,N]),
//        8=no bias, 16=TN (A is AT[K][M], leading dim ldat)
// ======================================================================
__global__ void __launch_bounds__(256)
sgemm64b(const float* __restrict__ A, const float* __restrict__ Bm,
         const float* __restrict__ bias, float* __restrict__ C,
         int M, int N, int K, int flags, int ldat) {
    __shared__ __align__(16) float As[16][64];
    __shared__ __align__(16) float Bs[16][128];

    int tid = threadIdx.x;
    int m0 = blockIdx.y * 64, n0 = blockIdx.x * 128;
    int tm = (tid >> 4) * 4, tn = (tid & 15) * 8;

    float acc[4][8];
    #pragma unroll
    for (int i = 0; i < 4; i++)
        #pragma unroll
        for (int j = 0; j < 8; j++) acc[i][j] = 0.0f;

    for (int k0 = 0; k0 < K; k0 += 16) {
        if (flags & 16) {  // TN: A is AT[k][m]
            int kk = tid >> 4;
            int c  = (tid & 15) * 4;
            float4 va = *(const float4*)&A[(size_t)(k0 + kk) * ldat + m0 + c];
            *(float4*)&As[kk][c] = va;
        } else {
            int r  = tid >> 2;
            int kq = (tid & 3) * 4;
            float4 va = *(const float4*)&A[(size_t)(m0 + r) * K + k0 + kq];
            As[kq + 0][r] = va.x; As[kq + 1][r] = va.y;
            As[kq + 2][r] = va.z; As[kq + 3][r] = va.w;
        }
        if (flags & 4) {   // NN: W[k][n], leading dim N
            #pragma unroll
            for (int i = 0; i < 2; i++) {
                int idx = tid + i * 256;
                int kk = idx >> 5;
                int c  = (idx & 31) * 4;
                float4 vb = *(const float4*)&Bm[(size_t)(k0 + kk) * N + n0 + c];
                *(float4*)&Bs[kk][c] = vb;
            }
        } else {           // NT: B[n][k]
            #pragma unroll
            for (int i = 0; i < 2; i++) {
                int idx = tid + i * 256;
                int r  = idx >> 2;
                int kq = (idx & 3) * 4;
                float4 vb = *(const float4*)&Bm[(size_t)(n0 + r) * K + k0 + kq];
                Bs[kq + 0][r] = vb.x; Bs[kq + 1][r] = vb.y;
                Bs[kq + 2][r] = vb.z; Bs[kq + 3][r] = vb.w;
            }
        }
        __syncthreads();
        #pragma unroll
        for (int kk = 0; kk < 16; kk++) {
            float a[4], b[8];
            *(float4*)&a[0] = *(const float4*)&As[kk][tm];
            *(float4*)&b[0] = *(const float4*)&Bs[kk][tn];
            *(float4*)&b[4] = *(const float4*)&Bs[kk][tn + 4];
            #pragma unroll
            for (int i = 0; i < 4; i++)
                #pragma unroll
                for (int j = 0; j < 8; j++)
                    acc[i][j] += a[i] * b[j];
        }
        __syncthreads();
    }

    #pragma unroll
    for (int i = 0; i < 4; i++) {
        int m = m0 + tm + i;
        float* crow;
        if (flags & 2) { int b = m & 31, tt = m >> 5; crow = C + (size_t)(b * T_ + tt) * N; }
        else           { crow = C + (size_t)m * N; }
        #pragma unroll
        for (int j = 0; j < 8; j += 4) {
            float4 v;
            v.x = acc[i][j + 0]; v.y = acc[i][j + 1];
            v.z = acc[i][j + 2]; v.w = acc[i][j + 3];
            if (!(flags & 8)) {
                v.x += bias[n0 + tn + j + 0]; v.y += bias[n0 + tn + j + 1];
                v.z += bias[n0 + tn + j + 2]; v.w += bias[n0 + tn + j + 3];
            }
            if (flags & 1) {
                v.x = fmaxf(v.x, 0.0f); v.y = fmaxf(v.y, 0.0f);
                v.z = fmaxf(v.z, 0.0f); v.w = fmaxf(v.w, 0.0f);
            }
            *(float4*)&crow[n0 + tn + j] = v;
        }
    }
}

// ======================================================================
// Persistent LSTM: 128 blocks x 256 threads.
// h read DIRECTLY from global (ldcg) in the GEMM loop — each h element
// is consumed exactly once per block, so smem staging had zero reuse;
// direct loads overlap the 8MB/step broadcast with the FFMA phase.
// ======================================================================
#define SM_WS4   0
#define SM_PACC  (SM_WS4 + 16 * 128 * 16)
#define SM_CS    (SM_PACC + 8 * 16 * 32 * 4)
#define SM_TOTAL (SM_CS + 128 * 4)

__global__ void __launch_bounds__(256, 1)
k_lstm(const float* __restrict__ whh) {
    extern __shared__ char smem[];
    float4* ws4  = (float4*)(smem + SM_WS4);   // [r][q]  r=gate*4+jj
    float*  pacc = (float*) (smem + SM_PACC);  // [w][r][b]
    float*  cs   = (float*) (smem + SM_CS);    // [jj][b]

    int tid = threadIdx.x, lane = tid & 31, wrp = tid >> 5;
    int j0 = blockIdx.x * 4;

    // stage w_hh slice once
    #pragma unroll
    for (int i = 0; i < 8; i++) {
        int idx = i * 256 + tid;
        int r = idx >> 7, q = idx & 127;
        int rr = (r >> 2) * LH + j0 + (r & 3);
        ws4[r * 128 + q] = ((const float4*)whh)[(size_t)rr * 128 + q];
    }
    if (tid < 128) cs[tid] = 0.0f;
    __syncthreads();

    const int qbase = wrp * 16;
    const int pjj = tid >> 5;      // valid when tid < 128
    const int pb  = tid & 31;
    const size_t xbase = (size_t)(j0 + pjj) * ROWS + pb;
    const size_t gstr  = (size_t)LH * ROWS;

    // prefetch X for t=0
    float xg0 = 0, xg1 = 0, xg2 = 0, xg3 = 0;
    if (tid < 128) {
        xg0 = __ldcg(&d_XT[xbase + 0 * gstr]);
        xg1 = __ldcg(&d_XT[xbase + 1 * gstr]);
        xg2 = __ldcg(&d_XT[xbase + 2 * gstr]);
        xg3 = __ldcg(&d_XT[xbase + 3 * gstr]);
    }

    for (int t = 0; t < T_; t++) {
        const float4* hin = (const float4*)d_hbuf[t & 1];

        // prefetch next X (overlaps GEMM)
        float xn0 = 0, xn1 = 0, xn2 = 0, xn3 = 0;
        if (tid < 128 && t + 1 < T_) {
            size_t o = xbase + (t + 1) * 32;
            xn0 = __ldcg(&d_XT[o + 0 * gstr]);
            xn1 = __ldcg(&d_XT[o + 1 * gstr]);
            xn2 = __ldcg(&d_XT[o + 2 * gstr]);
            xn3 = __ldcg(&d_XT[o + 3 * gstr]);
        }

        // GEMM: warp owns q-slice [qbase, qbase+16); h loaded direct from L2
        ull alo[16], ahi[16];
        #pragma unroll
        for (int r = 0; r < 16; r++) { alo[r] = 0ULL; ahi[r] = 0ULL; }
        #pragma unroll
        for (int qq = 0; qq < 16; qq++) {
            float4 hv = __ldcg(&hin[(qbase + qq) * 32 + lane]);
            ull hlo = ((ull*)&hv)[0], hhi = ((ull*)&hv)[1];
            #pragma unroll
            for (int r = 0; r < 16; r++) {
                float4 wv = ws4[r * 128 + qbase + qq];
                ffma2(alo[r], ((ull*)&wv)[0], hlo);
                ffma2(ahi[r], ((ull*)&wv)[1], hhi);
            }
        }
        #pragma unroll
        for (int r = 0; r < 16; r++) {
            float2 a = *(float2*)&alo[r], b = *(float2*)&ahi[r];
            pacc[(wrp * 16 + r) * 32 + lane] = a.x + a.y + b.x + b.y;
        }
        __syncthreads();

        // merged reduce + pointwise (tid < 128): warp=jj, lane=b
        if (tid < 128) {
            float zi = xg0, zf = xg1, zg = xg2, zo = xg3;
            #pragma unroll
            for (int w = 0; w < 8; w++) {
                const float* pw = pacc + (w * 16) * 32 + pb;
                zi += pw[( 0 + pjj) * 32];
                zf += pw[( 4 + pjj) * 32];
                zg += pw[( 8 + pjj) * 32];
                zo += pw[(12 + pjj) * 32];
            }
            float cp = cs[pjj * 32 + pb];
            float ig = sigm(zi), fg = sigm(zf);
            float gg = tanh_fast(zg), og = sigm(zo);
            float cn = fg * cp + ig * gg;
            float hn = og * tanh_fast(cn);
            cs[pjj * 32 + pb] = cn;
            d_hbuf[(t + 1) & 1][blockIdx.x * 128 + pb * 4 + pjj] = hn;
            d_LT[(size_t)(j0 + pjj) * ROWS + t * 32 + pb] = hn;
        }
        xg0 = xn0; xg1 = xn1; xg2 = xn2; xg3 = xn3;

        // device-wide barrier: release-add + acquire-spin by tid0
        __syncthreads();
        if (tid == 0) {
            red_release_add(&d_bar, 1);
            while (ld_acq(&d_bar) < NBLK * (t + 1)) { }
        }
        __syncthreads();
    }
}

// ======================================================================
extern "C" void kernel_launch(void* const* d_in, const int* in_sizes, int n_in,
                              void* d_out, int out_size) {
    const float* traj      = (const float*)d_in[0];
    const float* gcn_w     = (const float*)d_in[1];
    const float* gcn_b     = (const float*)d_in[2];
    const float* in_proj_w = (const float*)d_in[3];
    const float* in_proj_b = (const float*)d_in[4];
    const float* out_proj_w= (const float*)d_in[5];
    const float* out_proj_b= (const float*)d_in[6];
    // d_in[7]=va_w, d_in[8]=va_b : unused (uniform softmaxes)
    const float* w_ih      = (const float*)d_in[9];
    const float* w_hh      = (const float*)d_in[10];
    const float* b_ih      = (const float*)d_in[11];
    const float* b_hh      = (const float*)d_in[12];
    const float* lin1_w    = (const float*)d_in[13];
    const float* lin1_b    = (const float*)d_in[14];
    const float* lin2_w    = (const float*)d_in[15];
    const float* lin2_b    = (const float*)d_in[16];
    float* out = (float*)d_out;

    float *pG, *pF1, *pWbig, *pbihh, *pXT, *pLT, *pH1;
    cudaGetSymbolAddress((void**)&pG,    d_G);
    cudaGetSymbolAddress((void**)&pF1,   d_F1);
    cudaGetSymbolAddress((void**)&pWbig, d_Wbig);
    cudaGetSymbolAddress((void**)&pbihh, d_bihh);
    cudaGetSymbolAddress((void**)&pXT,   d_XT);
    cudaGetSymbolAddress((void**)&pLT,   d_LT);
    cudaGetSymbolAddress((void**)&pH1,   d_H1);

    static int smem_set = 0;
    if (!smem_set) {
        cudaFuncSetAttribute(k_lstm, cudaFuncAttributeMaxDynamicSharedMemorySize,
                             SM_TOTAL);
        smem_set = 1;
    }

    const float* bv = in_proj_b + 2 * D_;

    // launch 0: G + zero h + barrier reset
    k_init<<<ROWS, 256>>>(traj, gcn_w, gcn_b);
    // launch 1: fused bias chain
    k_bias<<<1, 1024>>>(out_proj_w, out_proj_b, bv, w_ih, b_ih, b_hh);
    // launch 2: F1 = w_ih @ Wop
    sgemm64b<<<dim3(D_ / 128, G4 / 64), 256>>>(
        w_ih, out_proj_w, nullptr, pF1, G4, D_, D_, 4 | 8, 0);
    // launch 3: Wbig = F1 @ Wv
    sgemm64b<<<dim3(D_ / 128, G4 / 64), 256>>>(
        pF1, in_proj_w + (size_t)2 * D_ * D_, nullptr, pWbig, G4, D_, D_, 4 | 8, 0);
    // launch 4: XT = Wbig @ G^T + bias_x[m]
    sgemm_nt_bm<<<dim3(ROWS / 128, G4 / 128), 256>>>(
        pWbig, pG, pbihh, pXT, G4, ROWS, D_);
    // launch 5: persistent LSTM  (ncu -s 5 captures THIS)
    k_lstm<<<NBLK, 256, SM_TOTAL>>>(w_hh);
    // launch 6: H1 = relu(L @ lin1_w^T + b) via TN
    sgemm64b<<<dim3(D_ / 128, ROWS / 64), 256>>>(
        pLT, lin1_w, lin1_b, pH1, ROWS, D_, LH, 1 | 16, ROWS);
    // launch 7: out = H1 @ lin2_w^T + b, permuted store
    sgemm64b<<<dim3(128 / 128, ROWS / 64), 256>>>(
        pH1, lin2_w, lin2_b, out, ROWS, 128, D_, 2, 0);
}

// round 11
// speedup vs baseline: 1.8075x; 1.1207x over previous
#include <cuda_runtime.h>
#include <math.h>

// ----- problem dims -----
#define B_    32
#define T_    100
#define NN_   32
#define F_    8
#define D_    256
#define LH    512
#define G4    2048      // 4*LH
#define ROWS  3200      // B_*T_  (row = t*32 + b)
#define NBLK  128       // persistent LSTM grid

typedef unsigned long long ull;

// ----- device scratch -----
__device__ float d_G   [ROWS * D_];
__device__ float d_Pk  [2 * G4 * D_]; // split-K partials
__device__ float d_F1  [G4 * D_];     // w_ih @ Wop
__device__ float d_Wbig[G4 * D_];     // w_ih @ Wop @ Wv
__device__ float d_batt[D_];          // Wop@bv + bop
__device__ float d_bihh[G4];          // w_ih@batt + b_ih + b_hh
__device__ float d_XT  [G4 * ROWS];   // X^T: [gate*512+j][t*32+b]
// hidden state, float4-grouped k-major: element (j,b) at (j>>2)*128 + b*4 + (j&3)
__device__ float d_hbuf[2][B_ * LH];
__device__ float d_LT  [LH * ROWS];   // L^T: [j][t*32+b]
__device__ float d_H1  [ROWS * D_];
__device__ int   d_bar;               // central barrier counter

__device__ __forceinline__ void ffma2(ull& d, ull a, ull b) {
    asm("fma.rn.f32x2 %0, %1, %2, %0;" : "+l"(d) : "l"(a), "l"(b));
}
__device__ __forceinline__ float tanh_fast(float x) {
    float ax = fabsf(x);
    float e  = __expf(-2.0f * ax);
    float t  = __fdividef(1.0f - e, 1.0f + e);
    return copysignf(t, x);
}
__device__ __forceinline__ float sigm(float x) {
    return 1.0f / (1.0f + __expf(-x));
}
__device__ __forceinline__ void red_release_add(int* p, int v) {
    asm volatile("red.release.gpu.global.add.s32 [%0], %1;" :: "l"(p), "r"(v) : "memory");
}
__device__ __forceinline__ int ld_acq(const int* p) {
    int v;
    asm volatile("ld.acquire.gpu.global.b32 %0, [%1];" : "=r"(v) : "l"(p) : "memory");
    return v;
}

// ======================================================================
// k_init: G = relu(mean_n(traj) @ gcn_w + gcn_b); also zero h[0], bar
// ======================================================================
__global__ void k_init(const float* __restrict__ traj,
                       const float* __restrict__ gw,
                       const float* __restrict__ gb) {
    int row = blockIdx.x;
    int t = row >> 5, b = row & 31;
    __shared__ float s[NN_ * F_];
    __shared__ float m[F_];
    int tid = threadIdx.x;

    if (row < 64) d_hbuf[0][row * 256 + tid] = 0.0f;
    if (row == 0 && tid == 0) d_bar = 0;

    const float* p = traj + (size_t)((b * T_ + t) * NN_) * F_;
    s[tid] = p[tid];
    __syncthreads();
    if (tid < F_) {
        float acc = 0.0f;
        #pragma unroll
        for (int n = 0; n < NN_; n++) acc += s[n * F_ + tid];
        m[tid] = acc * (1.0f / 32.0f);
    }
    __syncthreads();
    float acc = gb[tid];
    #pragma unroll
    for (int f = 0; f < F_; f++) acc += m[f] * gw[f * D_ + tid];
    d_G[(size_t)row * D_ + tid] = fmaxf(acc, 0.0f);
}

// ======================================================================
// GEMV (warp-per-row): out[j] = dot(W[j,:K], x) + add1[j] (+ add2[j])
// ======================================================================
__global__ void k_gemv(const float* __restrict__ W, int K,
                       const float* __restrict__ x,
                       const float* __restrict__ add1,
                       const float* __restrict__ add2,
                       float* __restrict__ out, int M) {
    int gw   = (blockIdx.x * blockDim.x + threadIdx.x) >> 5;
    int lane = threadIdx.x & 31;
    if (gw >= M) return;
    float s = 0.0f;
    for (int k = lane; k < K; k += 32)
        s += W[(size_t)gw * K + k] * x[k];
    #pragma unroll
    for (int off = 16; off > 0; off >>= 1)
        s += __shfl_xor_sync(0xffffffff, s, off);
    if (lane == 0) {
        float r = s + add1[gw];
        if (add2) r += add2[gw];
        out[gw] = r;
    }
}

// ======================================================================
// k_add: C[i] = P[i] + P[len + i]  (float4 elements)
// ======================================================================
__global__ void k_add(const float* __restrict__ P, float* __restrict__ C, int len4) {
    int i = blockIdx.x * blockDim.x + threadIdx.x;
    if (i < len4) {
        float4 a = ((const float4*)P)[i];
        float4 b = ((const float4*)P)[len4 + i];
        ((float4*)C)[i] = make_float4(a.x + b.x, a.y + b.y, a.z + b.z, a.w + b.w);
    }
}

// ======================================================================
// SGEMM-NT (proven, occ 2): C[M,N] = A[M,K] @ B[N,K]^T + biasM[m]
// BM=BN=128, BK=16, 256 threads, 8x8 micro-tile.
// ======================================================================
__global__ void __launch_bounds__(256)
sgemm_nt_bm(const float* __restrict__ A, const float* __restrict__ Bm,
            const float* __restrict__ biasM, float* __restrict__ C,
            int M, int N, int K) {
    __shared__ __align__(16) float As[16][128];
    __shared__ __align__(16) float Bs[16][128];

    int tid = threadIdx.x;
    int m0 = blockIdx.y * 128, n0 = blockIdx.x * 128;
    int tm = (tid >> 4) * 8, tn = (tid & 15) * 8;

    float acc[8][8];
    #pragma unroll
    for (int i = 0; i < 8; i++)
        #pragma unroll
        for (int j = 0; j < 8; j++) acc[i][j] = 0.0f;

    for (int k0 = 0; k0 < K; k0 += 16) {
        #pragma unroll
        for (int i = 0; i < 2; i++) {
            int idx = tid + i * 256;
            int r  = idx >> 2;
            int kq = (idx & 3) * 4;
            float4 va = *(const float4*)&A [(size_t)(m0 + r) * K + k0 + kq];
            As[kq + 0][r] = va.x; As[kq + 1][r] = va.y;
            As[kq + 2][r] = va.z; As[kq + 3][r] = va.w;
            float4 vb = *(const float4*)&Bm[(size_t)(n0 + r) * K + k0 + kq];
            Bs[kq + 0][r] = vb.x; Bs[kq + 1][r] = vb.y;
            Bs[kq + 2][r] = vb.z; Bs[kq + 3][r] = vb.w;
        }
        __syncthreads();
        #pragma unroll
        for (int kk = 0; kk < 16; kk++) {
            float a[8], b[8];
            *(float4*)&a[0] = *(const float4*)&As[kk][tm];
            *(float4*)&a[4] = *(const float4*)&As[kk][tm + 4];
            *(float4*)&b[0] = *(const float4*)&Bs[kk][tn];
            *(float4*)&b[4] = *(const float4*)&Bs[kk][tn + 4];
            #pragma unroll
            for (int i = 0; i < 8; i++)
                #pragma unroll
                for (int j = 0; j < 8; j++)
                    acc[i][j] += a[i] * b[j];
        }
        __syncthreads();
    }

    #pragma unroll
    for (int i = 0; i < 8; i++) {
        float bm = biasM[m0 + tm + i];
        float* crow = C + (size_t)(m0 + tm + i) * N;
        #pragma unroll
        for (int j = 0; j < 8; j += 4) {
            float4 v;
            v.x = acc[i][j + 0] + bm; v.y = acc[i][j + 1] + bm;
            v.z = acc[i][j + 2] + bm; v.w = acc[i][j + 3] + bm;
            *(float4*)&crow[n0 + tn + j] = v;
        }
    }
}

// ======================================================================
// SGEMM BM=64 BN=128 BK=16, 256 threads, 4x8 micro-tile.
// flags: 1=relu, 2=permute rows, 4=NN (B is W[K,N], ld ldb), 8=no bias,
//        16=TN (A is AT[K][M], ld lda), 32=split-K (part z: A+=z*kadvA,
//        B+=z*kadvB, C+=z*M*N)
// lda: A leading dim (row-major: per-row; TN: per-k-row)
// ldb: B leading dim (NT: per-n-row; NN: per-k-row)
// ======================================================================
__global__ void __launch_bounds__(256)
sgemm64b(const float* __restrict__ A, const float* __restrict__ Bm,
         const float* __restrict__ bias, float* __restrict__ C,
         int M, int N, int K, int flags, int lda, int ldb,
         size_t kadvA, size_t kadvB) {
    __shared__ __align__(16) float As[16][64];
    __shared__ __align__(16) float Bs[16][128];

    int tid = threadIdx.x;
    int m0 = blockIdx.y * 64, n0 = blockIdx.x * 128;
    int tm = (tid >> 4) * 4, tn = (tid & 15) * 8;

    if (flags & 32) {
        A  += blockIdx.z * kadvA;
        Bm += blockIdx.z * kadvB;
        C  += (size_t)blockIdx.z * M * N;
    }

    float acc[4][8];
    #pragma unroll
    for (int i = 0; i < 4; i++)
        #pragma unroll
        for (int j = 0; j < 8; j++) acc[i][j] = 0.0f;

    for (int k0 = 0; k0 < K; k0 += 16) {
        if (flags & 16) {  // TN: A is AT[k][m], ld lda
            int kk = tid >> 4;
            int c  = (tid & 15) * 4;
            float4 va = *(const float4*)&A[(size_t)(k0 + kk) * lda + m0 + c];
            *(float4*)&As[kk][c] = va;
        } else {           // A row-major [m][k], ld lda
            int r  = tid >> 2;
            int kq = (tid & 3) * 4;
            float4 va = *(const float4*)&A[(size_t)(m0 + r) * lda + k0 + kq];
            As[kq + 0][r] = va.x; As[kq + 1][r] = va.y;
            As[kq + 2][r] = va.z; As[kq + 3][r] = va.w;
        }
        if (flags & 4) {   // NN: W[k][n], ld ldb
            #pragma unroll
            for (int i = 0; i < 2; i++) {
                int idx = tid + i * 256;
                int kk = idx >> 5;
                int c  = (idx & 31) * 4;
                float4 vb = *(const float4*)&Bm[(size_t)(k0 + kk) * ldb + n0 + c];
                *(float4*)&Bs[kk][c] = vb;
            }
        } else {           // NT: B[n][k], ld ldb
            #pragma unroll
            for (int i = 0; i < 2; i++) {
                int idx = tid + i * 256;
                int r  = idx >> 2;
                int kq = (idx & 3) * 4;
                float4 vb = *(const float4*)&Bm[(size_t)(n0 + r) * ldb + k0 + kq];
                Bs[kq + 0][r] = vb.x; Bs[kq + 1][r] = vb.y;
                Bs[kq + 2][r] = vb.z; Bs[kq + 3][r] = vb.w;
            }
        }
        __syncthreads();
        #pragma unroll
        for (int kk = 0; kk < 16; kk++) {
            float a[4], b[8];
            *(float4*)&a[0] = *(const float4*)&As[kk][tm];
            *(float4*)&b[0] = *(const float4*)&Bs[kk][tn];
            *(float4*)&b[4] = *(const float4*)&Bs[kk][tn + 4];
            #pragma unroll
            for (int i = 0; i < 4; i++)
                #pragma unroll
                for (int j = 0; j < 8; j++)
                    acc[i][j] += a[i] * b[j];
        }
        __syncthreads();
    }

    #pragma unroll
    for (int i = 0; i < 4; i++) {
        int m = m0 + tm + i;
        float* crow;
        if (flags & 2) { int b = m & 31, tt = m >> 5; crow = C + (size_t)(b * T_ + tt) * N; }
        else           { crow = C + (size_t)m * N; }
        #pragma unroll
        for (int j = 0; j < 8; j += 4) {
            float4 v;
            v.x = acc[i][j + 0]; v.y = acc[i][j + 1];
            v.z = acc[i][j + 2]; v.w = acc[i][j + 3];
            if (!(flags & 8)) {
                v.x += bias[n0 + tn + j + 0]; v.y += bias[n0 + tn + j + 1];
                v.z += bias[n0 + tn + j + 2]; v.w += bias[n0 + tn + j + 3];
            }
            if (flags & 1) {
                v.x = fmaxf(v.x, 0.0f); v.y = fmaxf(v.y, 0.0f);
                v.z = fmaxf(v.z, 0.0f); v.w = fmaxf(v.w, 0.0f);
            }
            *(float4*)&crow[n0 + tn + j] = v;
        }
    }
}

// ======================================================================
// Persistent LSTM: 128 blocks x 256 threads (R9, direct-h).
// ======================================================================
#define SM_WS4   0
#define SM_PACC  (SM_WS4 + 16 * 128 * 16)
#define SM_CS    (SM_PACC + 8 * 16 * 32 * 4)
#define SM_TOTAL (SM_CS + 128 * 4)

__global__ void __launch_bounds__(256, 1)
k_lstm(const float* __restrict__ whh) {
    extern __shared__ char smem[];
    float4* ws4  = (float4*)(smem + SM_WS4);   // [r][q]  r=gate*4+jj
    float*  pacc = (float*) (smem + SM_PACC);  // [w][r][b]
    float*  cs   = (float*) (smem + SM_CS);    // [jj][b]

    int tid = threadIdx.x, lane = tid & 31, wrp = tid >> 5;
    int j0 = blockIdx.x * 4;

    #pragma unroll
    for (int i = 0; i < 8; i++) {
        int idx = i * 256 + tid;
        int r = idx >> 7, q = idx & 127;
        int rr = (r >> 2) * LH + j0 + (r & 3);
        ws4[r * 128 + q] = ((const float4*)whh)[(size_t)rr * 128 + q];
    }
    if (tid < 128) cs[tid] = 0.0f;
    __syncthreads();

    const int qbase = wrp * 16;
    const int pjj = tid >> 5;
    const int pb  = tid & 31;
    const size_t xbase = (size_t)(j0 + pjj) * ROWS + pb;
    const size_t gstr  = (size_t)LH * ROWS;

    float xg0 = 0, xg1 = 0, xg2 = 0, xg3 = 0;
    if (tid < 128) {
        xg0 = __ldcg(&d_XT[xbase + 0 * gstr]);
        xg1 = __ldcg(&d_XT[xbase + 1 * gstr]);
        xg2 = __ldcg(&d_XT[xbase + 2 * gstr]);
        xg3 = __ldcg(&d_XT[xbase + 3 * gstr]);
    }

    for (int t = 0; t < T_; t++) {
        const float4* hin = (const float4*)d_hbuf[t & 1];

        float xn0 = 0, xn1 = 0, xn2 = 0, xn3 = 0;
        if (tid < 128 && t + 1 < T_) {
            size_t o = xbase + (t + 1) * 32;
            xn0 = __ldcg(&d_XT[o + 0 * gstr]);
            xn1 = __ldcg(&d_XT[o + 1 * gstr]);
            xn2 = __ldcg(&d_XT[o + 2 * gstr]);
            xn3 = __ldcg(&d_XT[o + 3 * gstr]);
        }

        ull alo[16], ahi[16];
        #pragma unroll
        for (int r = 0; r < 16; r++) { alo[r] = 0ULL; ahi[r] = 0ULL; }
        #pragma unroll
        for (int qq = 0; qq < 16; qq++) {
            float4 hv = __ldcg(&hin[(qbase + qq) * 32 + lane]);
            ull hlo = ((ull*)&hv)[0], hhi = ((ull*)&hv)[1];
            #pragma unroll
            for (int r = 0; r < 16; r++) {
                float4 wv = ws4[r * 128 + qbase + qq];
                ffma2(alo[r], ((ull*)&wv)[0], hlo);
                ffma2(ahi[r], ((ull*)&wv)[1], hhi);
            }
        }
        #pragma unroll
        for (int r = 0; r < 16; r++) {
            float2 a = *(float2*)&alo[r], b = *(float2*)&ahi[r];
            pacc[(wrp * 16 + r) * 32 + lane] = a.x + a.y + b.x + b.y;
        }
        __syncthreads();

        if (tid < 128) {
            float zi = xg0, zf = xg1, zg = xg2, zo = xg3;
            #pragma unroll
            for (int w = 0; w < 8; w++) {
                const float* pw = pacc + (w * 16) * 32 + pb;
                zi += pw[( 0 + pjj) * 32];
                zf += pw[( 4 + pjj) * 32];
                zg += pw[( 8 + pjj) * 32];
                zo += pw[(12 + pjj) * 32];
            }
            float cp = cs[pjj * 32 + pb];
            float ig = sigm(zi), fg = sigm(zf);
            float gg = tanh_fast(zg), og = sigm(zo);
            float cn = fg * cp + ig * gg;
            float hn = og * tanh_fast(cn);
            cs[pjj * 32 + pb] = cn;
            d_hbuf[(t + 1) & 1][blockIdx.x * 128 + pb * 4 + pjj] = hn;
            d_LT[(size_t)(j0 + pjj) * ROWS + t * 32 + pb] = hn;
        }
        xg0 = xn0; xg1 = xn1; xg2 = xn2; xg3 = xn3;

        __syncthreads();
        if (tid == 0) {
            red_release_add(&d_bar, 1);
            while (ld_acq(&d_bar) < NBLK * (t + 1)) { }
        }
        __syncthreads();
    }
}

// ======================================================================
extern "C" void kernel_launch(void* const* d_in, const int* in_sizes, int n_in,
                              void* d_out, int out_size) {
    const float* traj      = (const float*)d_in[0];
    const float* gcn_w     = (const float*)d_in[1];
    const float* gcn_b     = (const float*)d_in[2];
    const float* in_proj_w = (const float*)d_in[3];
    const float* in_proj_b = (const float*)d_in[4];
    const float* out_proj_w= (const float*)d_in[5];
    const float* out_proj_b= (const float*)d_in[6];
    // d_in[7]=va_w, d_in[8]=va_b : unused (uniform softmaxes)
    const float* w_ih      = (const float*)d_in[9];
    const float* w_hh      = (const float*)d_in[10];
    const float* b_ih      = (const float*)d_in[11];
    const float* b_hh      = (const float*)d_in[12];
    const float* lin1_w    = (const float*)d_in[13];
    const float* lin1_b    = (const float*)d_in[14];
    const float* lin2_w    = (const float*)d_in[15];
    const float* lin2_b    = (const float*)d_in[16];
    float* out = (float*)d_out;

    float *pG, *pPk, *pF1, *pWbig, *pbatt, *pbihh, *pXT, *pLT, *pH1;
    cudaGetSymbolAddress((void**)&pG,    d_G);
    cudaGetSymbolAddress((void**)&pPk,   d_Pk);
    cudaGetSymbolAddress((void**)&pF1,   d_F1);
    cudaGetSymbolAddress((void**)&pWbig, d_Wbig);
    cudaGetSymbolAddress((void**)&pbatt, d_batt);
    cudaGetSymbolAddress((void**)&pbihh, d_bihh);
    cudaGetSymbolAddress((void**)&pXT,   d_XT);
    cudaGetSymbolAddress((void**)&pLT,   d_LT);
    cudaGetSymbolAddress((void**)&pH1,   d_H1);

    static int smem_set = 0;
    if (!smem_set) {
        cudaFuncSetAttribute(k_lstm, cudaFuncAttributeMaxDynamicSharedMemorySize,
                             SM_TOTAL);
        smem_set = 1;
    }

    const float* bv = in_proj_b + 2 * D_;
    const float* Wv = in_proj_w + (size_t)2 * D_ * D_;
    const int KH = D_ / 2;                // 128 per split-K part

    k_init<<<ROWS, 256>>>(traj, gcn_w, gcn_b);

    // bias chain (parallel gemvs)
    k_gemv<<<32, 256>>>(out_proj_w, D_, bv, out_proj_b, nullptr, pbatt, D_);
    k_gemv<<<256, 256>>>(w_ih, D_, pbatt, b_ih, b_hh, pbihh, G4);

    // F1 = w_ih @ Wop  (NN split-K: A=w_ih[G4xD] lda=D, B=Wop[DxD] ldb=D)
    sgemm64b<<<dim3(D_ / 128, G4 / 64, 2), 256>>>(
        w_ih, out_proj_w, nullptr, pPk, G4, D_, KH, 4 | 8 | 32,
        D_, D_, (size_t)KH, (size_t)KH * D_);
    k_add<<<(G4 * D_ / 4 + 255) / 256, 256>>>(pPk, pF1, G4 * D_ / 4);

    // Wbig = F1 @ Wv   (NN split-K)
    sgemm64b<<<dim3(D_ / 128, G4 / 64, 2), 256>>>(
        pF1, Wv, nullptr, pPk, G4, D_, KH, 4 | 8 | 32,
        D_, D_, (size_t)KH, (size_t)KH * D_);
    k_add<<<(G4 * D_ / 4 + 255) / 256, 256>>>(pPk, pWbig, G4 * D_ / 4);

    // XT = Wbig @ G^T + bias_x[m]
    sgemm_nt_bm<<<dim3(ROWS / 128, G4 / 128), 256>>>(
        pWbig, pG, pbihh, pXT, G4, ROWS, D_);

    // persistent LSTM
    k_lstm<<<NBLK, 256, SM_TOTAL>>>(w_hh);

    // H1 = relu(L @ lin1_w^T + b)  TN: A=LT lda=ROWS, B=lin1_w[DxLH] ldb=LH
    sgemm64b<<<dim3(D_ / 128, ROWS / 64), 256>>>(
        pLT, lin1_w, lin1_b, pH1, ROWS, D_, LH, 1 | 16,
        ROWS, LH, 0, 0);

    // out = H1 @ lin2_w^T + b, permuted: A=H1 lda=D, B=lin2_w[128xD] ldb=D
    sgemm64b<<<dim3(128 / 128, ROWS / 64), 256>>>(
        pH1, lin2_w, lin2_b, out, ROWS, 128, D_, 2,
        D_, D_, 0, 0);
}